// round 9
// baseline (speedup 1.0000x reference)
#include <cuda_runtime.h>
#include <cuda_bf16.h>
#include <math.h>
#include <stdint.h>

#define BATCH 1024
#define DIN   256
#define HID   512
#define KOUT  32
#define NOUT  (DIN * KOUT)  // 8192

typedef __nv_bfloat16 bf16;

// Scratch (allocation-free rule -> __device__ globals)
__device__ bf16 g_xhi[BATCH * DIN],  g_xlo[BATCH * DIN];
__device__ bf16 g_w0hi[HID * DIN],   g_w0lo[HID * DIN];
__device__ bf16 g_w1hi[HID * HID],   g_w1lo[HID * HID];
__device__ bf16 g_w2hi[HID * HID],   g_w2lo[HID * HID];
__device__ bf16 g_h0hi[BATCH * HID], g_h0lo[BATCH * HID];
__device__ bf16 g_h1hi[BATCH * HID], g_h1lo[BATCH * HID];
__device__ bf16 g_h2hi[BATCH * HID], g_h2lo[BATCH * HID];
// int8 path for the big GEMM
__device__ int8_t  g_wq1[NOUT * HID], g_wq2[NOUT * HID];
__device__ int8_t  g_aq1[BATCH * HID], g_aq2[BATCH * HID];
__device__ unsigned g_wamax[NOUT];
__device__ unsigned g_aamax[BATCH];

// ---------------------------------------------------------------------------
// PTX helpers
// ---------------------------------------------------------------------------
__device__ __forceinline__ uint32_t smem_u32(const void* p) {
    uint32_t a;
    asm("{ .reg .u64 t; cvta.to.shared.u64 t, %1; cvt.u32.u64 %0, t; }" : "=r"(a) : "l"(p));
    return a;
}
__device__ __forceinline__ void ldm_x4(uint32_t* r, uint32_t addr) {
    asm volatile("ldmatrix.sync.aligned.m8n8.x4.shared.b16 {%0,%1,%2,%3}, [%4];"
                 : "=r"(r[0]), "=r"(r[1]), "=r"(r[2]), "=r"(r[3]) : "r"(addr));
}
__device__ __forceinline__ void mma_bf16(float* d, const uint32_t* a, const uint32_t* b) {
    asm volatile("mma.sync.aligned.m16n8k16.row.col.f32.bf16.bf16.f32 "
                 "{%0,%1,%2,%3}, {%4,%5,%6,%7}, {%8,%9}, {%0,%1,%2,%3};"
                 : "+f"(d[0]), "+f"(d[1]), "+f"(d[2]), "+f"(d[3])
                 : "r"(a[0]), "r"(a[1]), "r"(a[2]), "r"(a[3]), "r"(b[0]), "r"(b[1]));
}
__device__ __forceinline__ void mma_s8(int* d, const uint32_t* a, const uint32_t* b) {
    asm volatile("mma.sync.aligned.m16n8k32.row.col.s32.s8.s8.s32 "
                 "{%0,%1,%2,%3}, {%4,%5,%6,%7}, {%8,%9}, {%0,%1,%2,%3};"
                 : "+r"(d[0]), "+r"(d[1]), "+r"(d[2]), "+r"(d[3])
                 : "r"(a[0]), "r"(a[1]), "r"(a[2]), "r"(a[3]), "r"(b[0]), "r"(b[1]));
}
__device__ __forceinline__ void cp16(uint32_t dst, const void* src) {
    asm volatile("cp.async.cg.shared.global [%0], [%1], 16;" :: "r"(dst), "l"(src) : "memory");
}
__device__ __forceinline__ void cp_commit() {
    asm volatile("cp.async.commit_group;" ::: "memory");
}
template<int N> __device__ __forceinline__ void cp_wait() {
    asm volatile("cp.async.wait_group %0;" :: "n"(N) : "memory");
}
__device__ __forceinline__ void split2(float v, bf16& h, bf16& l) {
    h = __float2bfloat16(v);
    l = __float2bfloat16(v - __bfloat162float(h));
}
// min of (k % 255) over k in [a, a+32)
__device__ __forceinline__ int minmod255(int a) {
    return ((a + 31) / 255 > a / 255) ? 0 : (a % 255);
}
// min of (k % 255) over k in [a, a+64)
__device__ __forceinline__ int minmod255_64(int a) {
    return ((a + 63) / 255 > a / 255) ? 0 : (a % 255);
}

// ---------------------------------------------------------------------------
// zero amax arrays (every call -> deterministic)
// ---------------------------------------------------------------------------
__global__ void zero_amax_kernel() {
    for (int i = threadIdx.x; i < NOUT; i += 256) g_wamax[i] = 0u;
    for (int i = threadIdx.x; i < BATCH; i += 256) g_aamax[i] = 0u;
}

// ---------------------------------------------------------------------------
// Merged prep: Wout -> row amax (masked); x/W0/W1/W2 -> bf16 hi/lo splits.
// ---------------------------------------------------------------------------
#define T_WOUT (NOUT * HID / 4)            // 1048576
#define T_X    (T_WOUT + BATCH * DIN / 4)  // +65536
#define T_W0   (T_X + HID * DIN / 4)       // +32768
#define T_W1   (T_W0 + HID * HID / 4)      // +65536
#define T_W2   (T_W1 + HID * HID / 4)      // +65536

__global__ void __launch_bounds__(256) prep_kernel(
    const float* __restrict__ Wout, const float* __restrict__ x,
    const float* __restrict__ W0,   const float* __restrict__ W1,
    const float* __restrict__ W2)
{
    int t = blockIdx.x * 256 + threadIdx.x;
    if (t < T_WOUT) {
        int base = t * 4;
        int n = base >> 9, k0 = base & 511;
        int od = (n >> 5) - 1;
        float4 w4 = *(const float4*)(Wout + base);
        float wv[4] = {w4.x, w4.y, w4.z, w4.w};
        float mx = 0.0f;
        #pragma unroll
        for (int q = 0; q < 4; q++) {
            float v = (od >= ((k0 + q) % 255)) ? fabsf(wv[q]) : 0.0f;
            mx = fmaxf(mx, v);
        }
        // warp covers one 128-elem span inside a single row -> warp reduce
        unsigned bits = __float_as_uint(mx);
        bits = __reduce_max_sync(0xffffffffu, bits);
        if ((threadIdx.x & 31) == 0) atomicMax(&g_wamax[n], bits);
        return;
    }
    const float* src; bf16 *hi, *lo;
    int mode, ksh, base;
    if (t < T_X)       { src = x;  hi = g_xhi;  lo = g_xlo;  mode = -1; ksh = 8; base = (t - T_WOUT) * 4; }
    else if (t < T_W0) { src = W0; hi = g_w0hi; lo = g_w0lo; mode = 0;  ksh = 8; base = (t - T_X) * 4; }
    else if (t < T_W1) { src = W1; hi = g_w1hi; lo = g_w1lo; mode = 1;  ksh = 9; base = (t - T_W0) * 4; }
    else               { src = W2; hi = g_w2hi; lo = g_w2lo; mode = 1;  ksh = 9; base = (t - T_W1) * 4; }

    float4 v4 = *(const float4*)(src + base);
    float vv[4] = {v4.x, v4.y, v4.z, v4.w};
    int n = base >> ksh;
    int k0 = base & ((1 << ksh) - 1);
    int nd = n % 255;
    bf16 h[4], l[4];
    #pragma unroll
    for (int q = 0; q < 4; q++) {
        float v = vv[q];
        int k = k0 + q;
        if (mode == 0 && !(nd >= k)) v = 0.0f;
        if (mode == 1 && !(nd >= (k % 255))) v = 0.0f;
        split2(v, h[q], l[q]);
    }
    *(uint2*)(hi + base) = *(uint2*)h;
    *(uint2*)(lo + base) = *(uint2*)l;
}

// ---------------------------------------------------------------------------
// Quantize masked Wout -> int8 hi/lo using per-row amax.
// ---------------------------------------------------------------------------
__global__ void __launch_bounds__(256) quant_w_kernel(const float* __restrict__ Wout)
{
    int t = blockIdx.x * 256 + threadIdx.x;
    int base = t * 4;
    int n = base >> 9, k0 = base & 511;
    int od = (n >> 5) - 1;
    float amax = __uint_as_float(g_wamax[n]);
    float sinv = (amax > 0.0f) ? (127.0f / amax) : 0.0f;
    float4 w4 = *(const float4*)(Wout + base);
    float wv[4] = {w4.x, w4.y, w4.z, w4.w};
    char q1[4], q2[4];
    #pragma unroll
    for (int q = 0; q < 4; q++) {
        float v = (od >= ((k0 + q) % 255)) ? wv[q] : 0.0f;
        float tq = v * sinv;
        int i1 = __float2int_rn(tq);
        int i2 = __float2int_rn((tq - (float)i1) * 252.0f);
        q1[q] = (char)i1; q2[q] = (char)i2;
    }
    *(uint32_t*)(g_wq1 + base) = *(uint32_t*)q1;
    *(uint32_t*)(g_wq2 + base) = *(uint32_t*)q2;
}

// ---------------------------------------------------------------------------
// Quantize h2 (bf16 hi+lo reconstruct) -> int8 hi/lo using per-row amax.
// ---------------------------------------------------------------------------
__global__ void __launch_bounds__(256) quant_a_kernel()
{
    int t = blockIdx.x * 256 + threadIdx.x;
    int base = t * 4;
    int m = base >> 9;
    float amax = __uint_as_float(g_aamax[m]);
    float sinv = (amax > 0.0f) ? (127.0f / amax) : 0.0f;
    uint2 hbits = *(uint2*)(g_h2hi + base);
    uint2 lbits = *(uint2*)(g_h2lo + base);
    bf16* hp = (bf16*)&hbits; bf16* lp = (bf16*)&lbits;
    char q1[4], q2[4];
    #pragma unroll
    for (int q = 0; q < 4; q++) {
        float v = __bfloat162float(hp[q]) + __bfloat162float(lp[q]);
        float tq = v * sinv;
        int i1 = __float2int_rn(tq);
        int i2 = __float2int_rn((tq - (float)i1) * 252.0f);
        q1[q] = (char)i1; q2[q] = (char)i2;
    }
    *(uint32_t*)(g_aq1 + base) = *(uint32_t*)q1;
    *(uint32_t*)(g_aq2 + base) = *(uint32_t*)q2;
}

// ---------------------------------------------------------------------------
// Small-layer bf16 HMMA kernel (proven). AMAX: layer2 also records row amax.
// ---------------------------------------------------------------------------
template<int K, int MODE, bool AMAX>
__global__ void __launch_bounds__(128) layer_kernel(
    const bf16* __restrict__ Ahi, const bf16* __restrict__ Alo,
    const bf16* __restrict__ Whi, const bf16* __restrict__ Wlo,
    const float* __restrict__ bias,
    bf16* __restrict__ Chi, bf16* __restrict__ Clo)
{
    constexpr int NC = K / 32;
    constexpr int S = 3;
    constexpr uint32_t STG = 12288;
    extern __shared__ bf16 smL[];
    const int tid = threadIdx.x, lane = tid & 31, wn = tid >> 5;
    const int bm = blockIdx.y * 32;
    const int bn = ((int)gridDim.x - 1 - (int)blockIdx.x) * 64;
    const uint32_t sb = smem_u32(smL);

    const int md = (bn / 255 == (bn + 63) / 255) ? ((bn + 63) % 255) : 254;

    int act[NC]; int na = 0;
    #pragma unroll
    for (int kc = 0; kc < NC; kc++) {
        int mm = (MODE == 0) ? (32 * kc) : minmod255(32 * kc);
        if (md >= mm) act[na++] = kc;
    }

    auto load_stage = [&](int s, int kc) {
        uint32_t stg = sb + (uint32_t)s * STG;
        {
            int r = tid >> 2, c = tid & 3;
            uint32_t dsw = (uint32_t)(r * 64 + ((c ^ ((r >> 1) & 3)) << 4));
            size_t asrc = (size_t)(bm + r) * K + kc * 32 + c * 8;
            cp16(stg + dsw,         Ahi + asrc);
            cp16(stg + 2048u + dsw, Alo + asrc);
        }
        #pragma unroll
        for (int i = 0; i < 2; i++) {
            int idx = tid + i * 128;
            int r = idx >> 2, c = idx & 3;
            uint32_t dsw = (uint32_t)(r * 64 + ((c ^ ((r >> 1) & 3)) << 4));
            size_t wsrc = (size_t)(bn + r) * K + kc * 32 + c * 8;
            cp16(stg + 4096u + dsw, Whi + wsrc);
            cp16(stg + 8192u + dsw, Wlo + wsrc);
        }
    };

    int raby[2], swa[2];
    #pragma unroll
    for (int mi = 0; mi < 2; mi++) {
        int r = mi * 16 + (lane & 15);
        raby[mi] = r * 64;
        swa[mi] = (r >> 1) & 3;
    }
    const int hiA = lane >> 4;
    const int nloc = wn * 16 + (((lane >> 3) >> 1) << 3) + (lane & 7);
    const int rbby = nloc * 64, swb = (nloc >> 1) & 3, cbB = (lane >> 3) & 1;

    float acc[2][2][4];
    #pragma unroll
    for (int a = 0; a < 2; a++)
        #pragma unroll
        for (int bq = 0; bq < 2; bq++)
            #pragma unroll
            for (int q = 0; q < 4; q++) acc[a][bq][q] = 0.0f;

    #pragma unroll
    for (int s = 0; s < S - 1; s++) { if (s < na) load_stage(s, act[s]); cp_commit(); }

    #pragma unroll 1
    for (int ii = 0; ii < na; ii++) {
        cp_wait<S - 2>();
        __syncthreads();
        int ld = ii + S - 1;
        if (ld < na) load_stage(ld % S, act[ld]);
        cp_commit();

        uint32_t stg = sb + (uint32_t)(ii % S) * STG;
        #pragma unroll
        for (int k16 = 0; k16 < 2; k16++) {
            uint32_t a0[2][4], a1[2][4];
            #pragma unroll
            for (int mi = 0; mi < 2; mi++) {
                uint32_t off = (uint32_t)(raby[mi] + ((((k16 << 1) | hiA) ^ swa[mi]) << 4));
                ldm_x4(a0[mi], stg + off);
                ldm_x4(a1[mi], stg + 2048u + off);
            }
            uint32_t boff = (uint32_t)(rbby + ((((k16 << 1) | cbB) ^ swb) << 4));
            uint32_t bh[4];
            ldm_x4(bh, stg + 4096u + boff);
            #pragma unroll
            for (int mi = 0; mi < 2; mi++) {
                mma_bf16(acc[mi][0], a0[mi], &bh[0]);
                mma_bf16(acc[mi][1], a0[mi], &bh[2]);
                mma_bf16(acc[mi][0], a1[mi], &bh[0]);
                mma_bf16(acc[mi][1], a1[mi], &bh[2]);
            }
            uint32_t bl[4];
            ldm_x4(bl, stg + 8192u + boff);
            #pragma unroll
            for (int mi = 0; mi < 2; mi++) {
                mma_bf16(acc[mi][0], a0[mi], &bl[0]);
                mma_bf16(acc[mi][1], a0[mi], &bl[2]);
            }
        }
    }
    cp_wait<0>();

    const int r0 = bm + (lane >> 2);
    const int c0 = bn + wn * 16 + (lane & 3) * 2;
    float rmax[2][2] = {{0.0f, 0.0f}, {0.0f, 0.0f}};
    #pragma unroll
    for (int mi = 0; mi < 2; mi++) {
        #pragma unroll
        for (int nj = 0; nj < 2; nj++) {
            int c = c0 + nj * 8;
            float b0 = bias[c], b1 = bias[c + 1];
            float v00 = fmaxf(acc[mi][nj][0] + b0, 0.0f);
            float v01 = fmaxf(acc[mi][nj][1] + b1, 0.0f);
            float v10 = fmaxf(acc[mi][nj][2] + b0, 0.0f);
            float v11 = fmaxf(acc[mi][nj][3] + b1, 0.0f);
            if (AMAX) {
                rmax[mi][0] = fmaxf(rmax[mi][0], fmaxf(v00, v01));
                rmax[mi][1] = fmaxf(rmax[mi][1], fmaxf(v10, v11));
            }
            bf16 h0, l0, h1, l1;
            split2(v00, h0, l0); split2(v01, h1, l1);
            size_t o0 = (size_t)(r0 + mi * 16) * HID + c;
            *(__nv_bfloat162*)(Chi + o0) = __halves2bfloat162(h0, h1);
            *(__nv_bfloat162*)(Clo + o0) = __halves2bfloat162(l0, l1);
            split2(v10, h0, l0); split2(v11, h1, l1);
            size_t o1 = (size_t)(r0 + mi * 16 + 8) * HID + c;
            *(__nv_bfloat162*)(Chi + o1) = __halves2bfloat162(h0, h1);
            *(__nv_bfloat162*)(Clo + o1) = __halves2bfloat162(l0, l1);
        }
    }
    if (AMAX) {
        #pragma unroll
        for (int mi = 0; mi < 2; mi++)
            #pragma unroll
            for (int rr = 0; rr < 2; rr++) {
                float m = rmax[mi][rr];
                m = fmaxf(m, __shfl_xor_sync(0xffffffffu, m, 1));
                m = fmaxf(m, __shfl_xor_sync(0xffffffffu, m, 2));
                if ((lane & 3) == 0)
                    atomicMax(&g_aamax[r0 + mi * 16 + rr * 8], __float_as_uint(m));
            }
    }
}

// ---------------------------------------------------------------------------
// Big int8 IMMA GEMM: theta = dequant(Aq @ Wq^T) + bout.
// acc1 = A1W1 (exact int32), acc2 = A1W2 + A2W1; out = sa*sw*(acc1+acc2/252)+b.
// Tile 128m x 64n, K-chunk 64 (64B rows), 256 threads (8 warps 4m x 2n,
// warp 32x32), 3-stage cp.async, chunk-skip (granularity 64), heavy-first.
// ---------------------------------------------------------------------------
__global__ void __launch_bounds__(256) gemm_i8_kernel(const float* __restrict__ bias,
                                                     float* __restrict__ C)
{
    constexpr int NCK = HID / 64;  // 8
    constexpr int S = 3;
    constexpr uint32_t STG = 24576;
    extern __shared__ int8_t smq[];
    const int tid = threadIdx.x, lane = tid & 31, wrp = tid >> 5;
    const int wm = wrp >> 1, wn = wrp & 1;
    const int bm = blockIdx.y * 128;
    const int bn = ((int)gridDim.x - 1 - (int)blockIdx.x) * 64;
    const uint32_t sb = smem_u32(smq);

    const int T = bn >> 5;  // max od in this n-tile
    int act[NCK]; int na = 0;
    #pragma unroll
    for (int kc = 0; kc < NCK; kc++)
        if (minmod255_64(64 * kc) <= T) act[na++] = kc;

    auto load_stage = [&](int s, int kc) {
        uint32_t stg = sb + (uint32_t)s * STG;
        #pragma unroll
        for (int i = 0; i < 2; i++) {  // A: 128 rows x 64B
            int idx = tid + i * 256;
            int r = idx >> 2, c = idx & 3;
            uint32_t dsw = (uint32_t)(r * 64 + ((c ^ ((r >> 1) & 3)) << 4));
            size_t asrc = (size_t)(bm + r) * HID + kc * 64 + c * 16;
            cp16(stg + dsw,         g_aq1 + asrc);
            cp16(stg + 8192u + dsw, g_aq2 + asrc);
        }
        {   // W: 64 rows x 64B
            int r = tid >> 2, c = tid & 3;
            uint32_t dsw = (uint32_t)(r * 64 + ((c ^ ((r >> 1) & 3)) << 4));
            size_t wsrc = (size_t)(bn + r) * HID + kc * 64 + c * 16;
            cp16(stg + 16384u + dsw, g_wq1 + wsrc);
            cp16(stg + 20480u + dsw, g_wq2 + wsrc);
        }
    };

    int raby[2], swa[2];
    #pragma unroll
    for (int mi = 0; mi < 2; mi++) {
        int r = wm * 32 + mi * 16 + (lane & 15);
        raby[mi] = r * 64;
        swa[mi] = (r >> 1) & 3;
    }
    const int hiA = lane >> 4;
    int rbby[2], swb[2];
    #pragma unroll
    for (int p = 0; p < 2; p++) {
        int n = wn * 32 + p * 16 + (((lane >> 3) >> 1) << 3) + (lane & 7);
        rbby[p] = n * 64;
        swb[p] = (n >> 1) & 3;
    }
    const int cbB = (lane >> 3) & 1;

    int acc1[2][4][4], acc2[2][4][4];
    #pragma unroll
    for (int a = 0; a < 2; a++)
        #pragma unroll
        for (int bq = 0; bq < 4; bq++)
            #pragma unroll
            for (int q = 0; q < 4; q++) { acc1[a][bq][q] = 0; acc2[a][bq][q] = 0; }

    #pragma unroll
    for (int s = 0; s < S - 1; s++) { if (s < na) load_stage(s, act[s]); cp_commit(); }

    #pragma unroll 1
    for (int ii = 0; ii < na; ii++) {
        cp_wait<S - 2>();
        __syncthreads();
        int ld = ii + S - 1;
        if (ld < na) load_stage(ld % S, act[ld]);
        cp_commit();

        uint32_t stg = sb + (uint32_t)(ii % S) * STG;
        #pragma unroll
        for (int s32 = 0; s32 < 2; s32++) {   // two k32 steps per 64-K chunk
            uint32_t a1[2][4], a2[2][4];
            #pragma unroll
            for (int mi = 0; mi < 2; mi++) {
                uint32_t off = (uint32_t)(raby[mi] + ((((s32 << 1) | hiA) ^ swa[mi]) << 4));
                ldm_x4(a1[mi], stg + off);
                ldm_x4(a2[mi], stg + 8192u + off);
            }
            #pragma unroll
            for (int p = 0; p < 2; p++) {
                uint32_t boff = (uint32_t)(rbby[p] + ((((s32 << 1) | cbB) ^ swb[p]) << 4));
                uint32_t w1[4], w2[4];
                ldm_x4(w1, stg + 16384u + boff);
                ldm_x4(w2, stg + 20480u + boff);
                #pragma unroll
                for (int mi = 0; mi < 2; mi++) {
                    mma_s8(acc1[mi][p * 2 + 0], a1[mi], &w1[0]);
                    mma_s8(acc1[mi][p * 2 + 1], a1[mi], &w1[2]);
                    mma_s8(acc2[mi][p * 2 + 0], a1[mi], &w2[0]);
                    mma_s8(acc2[mi][p * 2 + 1], a1[mi], &w2[2]);
                    mma_s8(acc2[mi][p * 2 + 0], a2[mi], &w1[0]);
                    mma_s8(acc2[mi][p * 2 + 1], a2[mi], &w1[2]);
                }
            }
        }
    }
    cp_wait<0>();

    // Epilogue: dequant + bias
    const float i127 = 1.0f / 127.0f, i252 = 1.0f / 252.0f;
    const int r0 = bm + wm * 32 + (lane >> 2);
    const int cbase = bn + wn * 32 + (lane & 3) * 2;
    #pragma unroll
    for (int mi = 0; mi < 2; mi++) {
        int rA = r0 + mi * 16, rB = rA + 8;
        float saA = __uint_as_float(g_aamax[rA]) * i127;
        float saB = __uint_as_float(g_aamax[rB]) * i127;
        #pragma unroll
        for (int nj = 0; nj < 4; nj++) {
            int col = cbase + nj * 8;
            float sw0 = __uint_as_float(g_wamax[col]) * i127;
            float sw1 = __uint_as_float(g_wamax[col + 1]) * i127;
            float b0 = bias[col], b1 = bias[col + 1];
            float2 v0, v1;
            v0.x = saA * sw0 * ((float)acc1[mi][nj][0] + (float)acc2[mi][nj][0] * i252) + b0;
            v0.y = saA * sw1 * ((float)acc1[mi][nj][1] + (float)acc2[mi][nj][1] * i252) + b1;
            v1.x = saB * sw0 * ((float)acc1[mi][nj][2] + (float)acc2[mi][nj][2] * i252) + b0;
            v1.y = saB * sw1 * ((float)acc1[mi][nj][3] + (float)acc2[mi][nj][3] * i252) + b1;
            *(float2*)(C + (size_t)rA * NOUT + col) = v0;
            *(float2*)(C + (size_t)rB * NOUT + col) = v1;
        }
    }
}

// ---------------------------------------------------------------------------
// Fused log_px + forward chain (unchanged).
// ---------------------------------------------------------------------------
__global__ void __launch_bounds__(128) chain_kernel(
    const float* __restrict__ x, const float* __restrict__ theta,
    const float* __restrict__ ulpa, float* __restrict__ out)
{
    __shared__ float s_lpa[255 * 4];
    for (int d = threadIdx.x; d < 255; d += 128) {
        float u0 = ulpa[d * 4 + 0], u1 = ulpa[d * 4 + 1];
        float u2 = ulpa[d * 4 + 2], u3 = ulpa[d * 4 + 3];
        float m = fmaxf(fmaxf(u0, u1), fmaxf(u2, u3));
        float s = expf(u0 - m) + expf(u1 - m) + expf(u2 - m) + expf(u3 - m);
        float lse = m + logf(s);
        s_lpa[d * 4 + 0] = u0 - lse;
        s_lpa[d * 4 + 1] = u1 - lse;
        s_lpa[d * 4 + 2] = u2 - lse;
        s_lpa[d * 4 + 3] = u3 - lse;
    }
    __syncthreads();

    const int lane = threadIdx.x & 31;
    const int wid  = threadIdx.x >> 5;
    const int half = lane >> 4;
    const int l    = lane & 15;
    const int i    = l >> 2, j = l & 3;
    const int b    = (blockIdx.x * 4 + wid) * 2 + half;

    const unsigned FULL = 0xffffffffu;
    const float NL = -0.91893853320467274178f;

    const float* th = theta + (size_t)b * NOUT;
    const float* xb = x + (size_t)b * DIN;

    float carry;
    {
        float mu = __ldg(th + l), ls = __ldg(th + 16 + l);
        float xd = __ldg(xb);
        float sd = __expf(ls) + 0.01f;
        float z = __fdividef(xd - mu, sd);
        float lp = fmaf(-0.5f * z, z, NL) - __logf(sd);
        float v = lp + s_lpa[j];
        carry = __shfl_sync(FULL, v, half * 16 + j);
    }
    float mu = __ldg(th + 32 + l), ls = __ldg(th + 48 + l);
    float xd = __ldg(xb + 1);
    #pragma unroll 1
    for (int d = 1; d < 255; d++) {
        float nmu = __ldg(th + (d + 1) * 32 + l);
        float nls = __ldg(th + (d + 1) * 32 + 16 + l);
        float nxd = __ldg(xb + d + 1);
        float sd = __expf(ls) + 0.01f;
        float z = __fdividef(xd - mu, sd);
        float lp = fmaf(-0.5f * z, z, NL) - __logf(sd);
        float ci = __shfl_sync(FULL, carry, half * 16 + i);
        float tv = ci + lp + s_lpa[d * 4 + j];
        float m = fmaxf(tv, __shfl_xor_sync(FULL, tv, 4));
        m = fmaxf(m, __shfl_xor_sync(FULL, m, 8));
        float s = __expf(tv - m);
        s += __shfl_xor_sync(FULL, s, 4);
        s += __shfl_xor_sync(FULL, s, 8);
        carry = m + __logf(s);
        mu = nmu; ls = nls; xd = nxd;
    }
    {
        float sd = __expf(ls) + 0.01f;
        float z = __fdividef(xd - mu, sd);
        float lp = fmaf(-0.5f * z, z, NL) - __logf(sd);
        float ci = __shfl_sync(FULL, carry, half * 16 + i);
        float tv = (j == 0) ? (ci + lp) : -1e30f;
        float m = fmaxf(tv, __shfl_xor_sync(FULL, tv, 1));
        m = fmaxf(m, __shfl_xor_sync(FULL, m, 2));
        m = fmaxf(m, __shfl_xor_sync(FULL, m, 4));
        m = fmaxf(m, __shfl_xor_sync(FULL, m, 8));
        float s = __expf(tv - m);
        s += __shfl_xor_sync(FULL, s, 1);
        s += __shfl_xor_sync(FULL, s, 2);
        s += __shfl_xor_sync(FULL, s, 4);
        s += __shfl_xor_sync(FULL, s, 8);
        if (l == 0) out[b] = m + __logf(s);
    }
}

// ---------------------------------------------------------------------------
// kernel_launch
// ---------------------------------------------------------------------------
extern "C" void kernel_launch(void* const* d_in, const int* in_sizes, int n_in,
                              void* d_out, int out_size)
{
    const float* x    = (const float*)d_in[0];
    const float* W0   = (const float*)d_in[1];
    const float* b0   = (const float*)d_in[2];
    const float* W1   = (const float*)d_in[3];
    const float* b1   = (const float*)d_in[4];
    const float* W2   = (const float*)d_in[5];
    const float* b2   = (const float*)d_in[6];
    const float* Wout = (const float*)d_in[7];
    const float* bout = (const float*)d_in[8];
    const float* ulpa = (const float*)d_in[9];

    float* out   = (float*)d_out;
    float* theta = out + BATCH;

    bf16 *xhi, *xlo, *w0hi, *w0lo, *w1hi, *w1lo, *w2hi, *w2lo;
    bf16 *h0hi, *h0lo, *h1hi, *h1lo, *h2hi, *h2lo;
    cudaGetSymbolAddress((void**)&xhi, g_xhi);   cudaGetSymbolAddress((void**)&xlo, g_xlo);
    cudaGetSymbolAddress((void**)&w0hi, g_w0hi); cudaGetSymbolAddress((void**)&w0lo, g_w0lo);
    cudaGetSymbolAddress((void**)&w1hi, g_w1hi); cudaGetSymbolAddress((void**)&w1lo, g_w1lo);
    cudaGetSymbolAddress((void**)&w2hi, g_w2hi); cudaGetSymbolAddress((void**)&w2lo, g_w2lo);
    cudaGetSymbolAddress((void**)&h0hi, g_h0hi); cudaGetSymbolAddress((void**)&h0lo, g_h0lo);
    cudaGetSymbolAddress((void**)&h1hi, g_h1hi); cudaGetSymbolAddress((void**)&h1lo, g_h1lo);
    cudaGetSymbolAddress((void**)&h2hi, g_h2hi); cudaGetSymbolAddress((void**)&h2lo, g_h2lo);

    cudaFuncSetAttribute(gemm_i8_kernel,
                         cudaFuncAttributeMaxDynamicSharedMemorySize, 73728);
    cudaFuncSetAttribute(layer_kernel<DIN, 0, false>,
                         cudaFuncAttributeMaxDynamicSharedMemorySize, 36864);
    cudaFuncSetAttribute(layer_kernel<HID, 1, false>,
                         cudaFuncAttributeMaxDynamicSharedMemorySize, 36864);
    cudaFuncSetAttribute(layer_kernel<HID, 1, true>,
                         cudaFuncAttributeMaxDynamicSharedMemorySize, 36864);

    zero_amax_kernel<<<1, 256>>>();
    prep_kernel<<<(T_W2 + 255) / 256, 256>>>(Wout, x, W0, W1, W2);
    quant_w_kernel<<<NOUT * HID / 4 / 256, 256>>>(Wout);

    layer_kernel<DIN, 0, false><<<dim3(HID / 64, BATCH / 32), 128, 36864>>>(
        xhi, xlo, w0hi, w0lo, b0, h0hi, h0lo);
    layer_kernel<HID, 1, false><<<dim3(HID / 64, BATCH / 32), 128, 36864>>>(
        h0hi, h0lo, w1hi, w1lo, b1, h1hi, h1lo);
    layer_kernel<HID, 1, true><<<dim3(HID / 64, BATCH / 32), 128, 36864>>>(
        h1hi, h1lo, w2hi, w2lo, b2, h2hi, h2lo);

    quant_a_kernel<<<BATCH * HID / 4 / 256, 256>>>();

    gemm_i8_kernel<<<dim3(NOUT / 64, BATCH / 128), 256, 73728>>>(bout, theta);

    chain_kernel<<<BATCH / 8, 128>>>(x, theta, ulpa, out);
}

// round 10
// speedup vs baseline: 1.1203x; 1.1203x over previous
#include <cuda_runtime.h>
#include <cuda_bf16.h>
#include <math.h>
#include <stdint.h>

#define BATCH 1024
#define DIN   256
#define HID   512
#define KOUT  32
#define NOUT  (DIN * KOUT)  // 8192

typedef __nv_bfloat16 bf16;

// Scratch (allocation-free rule -> __device__ globals)
__device__ bf16 g_xhi[BATCH * DIN],  g_xlo[BATCH * DIN];
__device__ bf16 g_w0hi[HID * DIN],   g_w0lo[HID * DIN];
__device__ bf16 g_w1hi[HID * HID],   g_w1lo[HID * HID];
__device__ bf16 g_w2hi[HID * HID],   g_w2lo[HID * HID];
__device__ bf16 g_h0hi[BATCH * HID], g_h0lo[BATCH * HID];
__device__ bf16 g_h1hi[BATCH * HID], g_h1lo[BATCH * HID];
__device__ bf16 g_h2hi[BATCH * HID], g_h2lo[BATCH * HID];
__device__ bf16 g_whi[NOUT * HID],   g_wlo[NOUT * HID];

// ---------------------------------------------------------------------------
// PTX helpers (sm_80-baseline: ldmatrix / mma.sync / cp.async — tcgen05 is
// rejected by this toolchain's compute_103 stage; IMMA k32 measured 2x cost)
// ---------------------------------------------------------------------------
__device__ __forceinline__ uint32_t smem_u32(const void* p) {
    uint32_t a;
    asm("{ .reg .u64 t; cvta.to.shared.u64 t, %1; cvt.u32.u64 %0, t; }" : "=r"(a) : "l"(p));
    return a;
}
__device__ __forceinline__ void ldm_x4(uint32_t* r, uint32_t addr) {
    asm volatile("ldmatrix.sync.aligned.m8n8.x4.shared.b16 {%0,%1,%2,%3}, [%4];"
                 : "=r"(r[0]), "=r"(r[1]), "=r"(r[2]), "=r"(r[3]) : "r"(addr));
}
__device__ __forceinline__ void mma_bf16(float* d, const uint32_t* a, const uint32_t* b) {
    asm volatile("mma.sync.aligned.m16n8k16.row.col.f32.bf16.bf16.f32 "
                 "{%0,%1,%2,%3}, {%4,%5,%6,%7}, {%8,%9}, {%0,%1,%2,%3};"
                 : "+f"(d[0]), "+f"(d[1]), "+f"(d[2]), "+f"(d[3])
                 : "r"(a[0]), "r"(a[1]), "r"(a[2]), "r"(a[3]), "r"(b[0]), "r"(b[1]));
}
__device__ __forceinline__ void cp16(uint32_t dst, const void* src) {
    asm volatile("cp.async.cg.shared.global [%0], [%1], 16;" :: "r"(dst), "l"(src) : "memory");
}
__device__ __forceinline__ void cp_commit() {
    asm volatile("cp.async.commit_group;" ::: "memory");
}
template<int N> __device__ __forceinline__ void cp_wait() {
    asm volatile("cp.async.wait_group %0;" :: "n"(N) : "memory");
}
__device__ __forceinline__ void split2(float v, bf16& h, bf16& l) {
    h = __float2bfloat16(v);
    l = __float2bfloat16(v - __bfloat162float(h));
}
// min of (k % 255) over k in [a, a+32)
__device__ __forceinline__ int minmod255(int a) {
    return ((a + 31) / 255 > a / 255) ? 0 : (a % 255);
}

// ---------------------------------------------------------------------------
// Prep: split x, W0, W1, W2 into bf16 hi/lo with masks folded in.
// ---------------------------------------------------------------------------
__global__ void __launch_bounds__(256) prep_kernel(
    const float* __restrict__ x,  const float* __restrict__ W0,
    const float* __restrict__ W1, const float* __restrict__ W2)
{
    int t = blockIdx.x * 256 + threadIdx.x;
    const float* src; bf16 *hi, *lo;
    int mode, ksh, base;
    if (t < 65536)       { src = x;  hi = g_xhi;  lo = g_xlo;  mode = -1; ksh = 8; base = t * 4; }
    else if (t < 98304)  { src = W0; hi = g_w0hi; lo = g_w0lo; mode = 0;  ksh = 8; base = (t - 65536) * 4; }
    else if (t < 163840) { src = W1; hi = g_w1hi; lo = g_w1lo; mode = 1;  ksh = 9; base = (t - 98304) * 4; }
    else                 { src = W2; hi = g_w2hi; lo = g_w2lo; mode = 1;  ksh = 9; base = (t - 163840) * 4; }

    float4 v4 = *(const float4*)(src + base);
    float vv[4] = {v4.x, v4.y, v4.z, v4.w};
    int n = base >> ksh;
    int k0 = base & ((1 << ksh) - 1);
    int nd = n % 255;
    bf16 h[4], l[4];
    #pragma unroll
    for (int q = 0; q < 4; q++) {
        float v = vv[q];
        int k = k0 + q;
        if (mode == 0 && !(nd >= k)) v = 0.0f;
        if (mode == 1 && !(nd >= (k % 255))) v = 0.0f;
        split2(v, h[q], l[q]);
    }
    *(uint2*)(hi + base) = *(uint2*)h;
    *(uint2*)(lo + base) = *(uint2*)l;
}

// Wout split with output mask (MODE 2)
__global__ void __launch_bounds__(256) split_wout_kernel(const float* __restrict__ W)
{
    int idx = blockIdx.x * 256 + threadIdx.x;
    int base = idx * 4;
    int n = base >> 9, k0 = base & 511;
    int od = (n >> 5) - 1;
    float4 w4 = *(const float4*)(W + base);
    float wv[4] = {w4.x, w4.y, w4.z, w4.w};
    bf16 h[4], l[4];
    #pragma unroll
    for (int q = 0; q < 4; q++) {
        float v = (od >= ((k0 + q) % 255)) ? wv[q] : 0.0f;
        split2(v, h[q], l[q]);
    }
    *(uint2*)(g_whi + base) = *(uint2*)h;
    *(uint2*)(g_wlo + base) = *(uint2*)l;
}

// ---------------------------------------------------------------------------
// Small-layer HMMA kernel: C = relu(A @ W^T + b), split epilogue -> Chi/Clo.
// Tile 32m x 64n, BK=32, *256 threads* (8 warps = 2m x 4n, warp 16x16).
// Same instructions as R7's 128-thread version but 2x warps/SM for latency.
// 3-stage cp.async; dead K-chunks skipped exactly.
// ---------------------------------------------------------------------------
template<int K, int MODE>
__global__ void __launch_bounds__(256) layer_kernel(
    const bf16* __restrict__ Ahi, const bf16* __restrict__ Alo,
    const bf16* __restrict__ Whi, const bf16* __restrict__ Wlo,
    const float* __restrict__ bias,
    bf16* __restrict__ Chi, bf16* __restrict__ Clo)
{
    constexpr int NC = K / 32;
    constexpr int S = 3;
    constexpr uint32_t STG = 12288;
    extern __shared__ bf16 smL[];
    const int tid = threadIdx.x, lane = tid & 31, wrp = tid >> 5;
    const int wm = wrp >> 2, wn = wrp & 3;   // 2m x 4n warps
    const int bm = blockIdx.y * 32;
    const int bn = ((int)gridDim.x - 1 - (int)blockIdx.x) * 64;
    const uint32_t sb = smem_u32(smL);

    const int md = (bn / 255 == (bn + 63) / 255) ? ((bn + 63) % 255) : 254;

    int act[NC]; int na = 0;
    #pragma unroll
    for (int kc = 0; kc < NC; kc++) {
        int mm = (MODE == 0) ? (32 * kc) : minmod255(32 * kc);
        if (md >= mm) act[na++] = kc;
    }

    auto load_stage = [&](int s, int kc) {
        uint32_t stg = sb + (uint32_t)s * STG;
        if (tid < 128) {  // A: 32 rows x 64B, hi+lo
            int r = tid >> 2, c = tid & 3;
            uint32_t dsw = (uint32_t)(r * 64 + ((c ^ ((r >> 1) & 3)) << 4));
            size_t asrc = (size_t)(bm + r) * K + kc * 32 + c * 8;
            cp16(stg + dsw,         Ahi + asrc);
            cp16(stg + 2048u + dsw, Alo + asrc);
        }
        {   // W: 64 rows x 64B, hi+lo (all 256 threads)
            int r = tid >> 2, c = tid & 3;
            uint32_t dsw = (uint32_t)(r * 64 + ((c ^ ((r >> 1) & 3)) << 4));
            size_t wsrc = (size_t)(bn + r) * K + kc * 32 + c * 8;
            cp16(stg + 4096u + dsw, Whi + wsrc);
            cp16(stg + 8192u + dsw, Wlo + wsrc);
        }
    };

    // frag addresses: warp covers rows [wm*16, wm*16+16), cols [wn*16, wn*16+16)
    int raby, swa;
    {
        int r = wm * 16 + (lane & 15);
        raby = r * 64;
        swa = (r >> 1) & 3;
    }
    const int hiA = lane >> 4;
    const int nloc = wn * 16 + (((lane >> 3) >> 1) << 3) + (lane & 7);
    const int rbby = nloc * 64, swb = (nloc >> 1) & 3, cbB = (lane >> 3) & 1;

    float acc[2][4];
    #pragma unroll
    for (int bq = 0; bq < 2; bq++)
        #pragma unroll
        for (int q = 0; q < 4; q++) acc[bq][q] = 0.0f;

    #pragma unroll
    for (int s = 0; s < S - 1; s++) { if (s < na) load_stage(s, act[s]); cp_commit(); }

    #pragma unroll 1
    for (int ii = 0; ii < na; ii++) {
        cp_wait<S - 2>();
        __syncthreads();
        int ld = ii + S - 1;
        if (ld < na) load_stage(ld % S, act[ld]);
        cp_commit();

        uint32_t stg = sb + (uint32_t)(ii % S) * STG;
        #pragma unroll
        for (int k16 = 0; k16 < 2; k16++) {
            uint32_t a0[4], a1[4];
            uint32_t off = (uint32_t)(raby + ((((k16 << 1) | hiA) ^ swa) << 4));
            ldm_x4(a0, stg + off);
            ldm_x4(a1, stg + 2048u + off);
            uint32_t boff = (uint32_t)(rbby + ((((k16 << 1) | cbB) ^ swb) << 4));
            uint32_t bh[4];
            ldm_x4(bh, stg + 4096u + boff);
            mma_bf16(acc[0], a0, &bh[0]);
            mma_bf16(acc[1], a0, &bh[2]);
            mma_bf16(acc[0], a1, &bh[0]);
            mma_bf16(acc[1], a1, &bh[2]);
            uint32_t bl[4];
            ldm_x4(bl, stg + 8192u + boff);
            mma_bf16(acc[0], a0, &bl[0]);
            mma_bf16(acc[1], a0, &bl[2]);
        }
    }
    cp_wait<0>();

    // Epilogue: bias + relu + split -> bf16 hi/lo
    const int r0 = bm + wm * 16 + (lane >> 2);
    const int c0 = bn + wn * 16 + (lane & 3) * 2;
    #pragma unroll
    for (int nj = 0; nj < 2; nj++) {
        int c = c0 + nj * 8;
        float b0 = bias[c], b1 = bias[c + 1];
        float v00 = fmaxf(acc[nj][0] + b0, 0.0f);
        float v01 = fmaxf(acc[nj][1] + b1, 0.0f);
        float v10 = fmaxf(acc[nj][2] + b0, 0.0f);
        float v11 = fmaxf(acc[nj][3] + b1, 0.0f);
        bf16 h0, l0, h1, l1;
        split2(v00, h0, l0); split2(v01, h1, l1);
        size_t o0 = (size_t)r0 * HID + c;
        *(__nv_bfloat162*)(Chi + o0) = __halves2bfloat162(h0, h1);
        *(__nv_bfloat162*)(Clo + o0) = __halves2bfloat162(l0, l1);
        split2(v10, h0, l0); split2(v11, h1, l1);
        size_t o1 = (size_t)(r0 + 8) * HID + c;
        *(__nv_bfloat162*)(Chi + o1) = __halves2bfloat162(h0, h1);
        *(__nv_bfloat162*)(Clo + o1) = __halves2bfloat162(l0, l1);
    }
}

// ---------------------------------------------------------------------------
// Big HMMA GEMM: theta[1024,8192] = h2 @ Wout^T + bout (3-term split).
// Tile 128x128, BK=32, 256 threads, 3-stage pipeline, chunk-skip by mask,
// heavy tiles first (reversed bid). (EXACT R7 version — proven 176.9us.)
// ---------------------------------------------------------------------------
__global__ void __launch_bounds__(256) gemm_mma_kernel(
    const bf16* __restrict__ Ahi, const bf16* __restrict__ Alo,
    const bf16* __restrict__ Whi, const bf16* __restrict__ Wlo,
    const float* __restrict__ bias, float* __restrict__ C)
{
    constexpr int NC = HID / 32;   // 16
    constexpr int S = 3;
    extern __shared__ bf16 smd[];
    const int tid = threadIdx.x, lane = tid & 31, wrp = tid >> 5;
    const int wm = wrp >> 2, wn = wrp & 3;
    const int bm = blockIdx.y * 128;
    const int bn = ((int)gridDim.x - 1 - (int)blockIdx.x) * 128;
    const uint32_t sb = smem_u32(smd);

    const int T = (bn >> 5) + 2;
    int act[NC]; int na = 0;
    #pragma unroll
    for (int kc = 0; kc < NC; kc++)
        if (minmod255(32 * kc) <= T) act[na++] = kc;

    auto load_stage = [&](int s, int kc) {
        uint32_t stg = sb + (uint32_t)s * 32768u;
        #pragma unroll
        for (int i = 0; i < 2; i++) {
            int idx = tid + i * 256;
            int r = idx >> 2, c = idx & 3;
            uint32_t dsw = (uint32_t)(r * 64 + ((c ^ ((r >> 1) & 3)) << 4));
            size_t asrc = (size_t)(bm + r) * HID + kc * 32 + c * 8;
            size_t wsrc = (size_t)(bn + r) * HID + kc * 32 + c * 8;
            cp16(stg + dsw,          Ahi + asrc);
            cp16(stg + 8192u + dsw,  Alo + asrc);
            cp16(stg + 16384u + dsw, Whi + wsrc);
            cp16(stg + 24576u + dsw, Wlo + wsrc);
        }
    };

    int raby[4], swa[4];
    #pragma unroll
    for (int mi = 0; mi < 4; mi++) {
        int r = wm * 64 + mi * 16 + (lane & 15);
        raby[mi] = r * 64;
        swa[mi] = (r >> 1) & 3;
    }
    const int hiA = lane >> 4;
    int rbby[2], swb[2];
    #pragma unroll
    for (int p = 0; p < 2; p++) {
        int n = wn * 32 + p * 16 + (((lane >> 3) >> 1) << 3) + (lane & 7);
        rbby[p] = n * 64;
        swb[p] = (n >> 1) & 3;
    }
    const int cbB = (lane >> 3) & 1;

    float acc[4][4][4];
    #pragma unroll
    for (int a = 0; a < 4; a++)
        #pragma unroll
        for (int bq = 0; bq < 4; bq++)
            #pragma unroll
            for (int q = 0; q < 4; q++) acc[a][bq][q] = 0.0f;

    #pragma unroll
    for (int s = 0; s < S - 1; s++) { if (s < na) load_stage(s, act[s]); cp_commit(); }

    #pragma unroll 1
    for (int ii = 0; ii < na; ii++) {
        cp_wait<S - 2>();
        __syncthreads();
        int ld = ii + S - 1;
        if (ld < na) load_stage(ld % S, act[ld]);
        cp_commit();

        uint32_t stg = sb + (uint32_t)(ii % S) * 32768u;
        #pragma unroll
        for (int k16 = 0; k16 < 2; k16++) {
            uint32_t a0[4][4], a1[4][4];
            #pragma unroll
            for (int mi = 0; mi < 4; mi++) {
                uint32_t off = (uint32_t)(raby[mi] + ((((k16 << 1) | hiA) ^ swa[mi]) << 4));
                ldm_x4(a0[mi], stg + off);
                ldm_x4(a1[mi], stg + 8192u + off);
            }
            #pragma unroll
            for (int p = 0; p < 2; p++) {
                uint32_t boff = (uint32_t)(rbby[p] + ((((k16 << 1) | cbB) ^ swb[p]) << 4));
                uint32_t bh[4];
                ldm_x4(bh, stg + 16384u + boff);
                #pragma unroll
                for (int mi = 0; mi < 4; mi++) {
                    mma_bf16(acc[mi][p * 2 + 0], a0[mi], &bh[0]);
                    mma_bf16(acc[mi][p * 2 + 1], a0[mi], &bh[2]);
                    mma_bf16(acc[mi][p * 2 + 0], a1[mi], &bh[0]);
                    mma_bf16(acc[mi][p * 2 + 1], a1[mi], &bh[2]);
                }
                uint32_t bl[4];
                ldm_x4(bl, stg + 24576u + boff);
                #pragma unroll
                for (int mi = 0; mi < 4; mi++) {
                    mma_bf16(acc[mi][p * 2 + 0], a0[mi], &bl[0]);
                    mma_bf16(acc[mi][p * 2 + 1], a0[mi], &bl[2]);
                }
            }
        }
    }
    cp_wait<0>();

    const int r0 = bm + wm * 64 + (lane >> 2);
    const int cbase = bn + wn * 32 + (lane & 3) * 2;
    #pragma unroll
    for (int mi = 0; mi < 4; mi++) {
        #pragma unroll
        for (int nj = 0; nj < 4; nj++) {
            int col = cbase + nj * 8;
            float b0 = bias[col], b1 = bias[col + 1];
            float2 v0 = {acc[mi][nj][0] + b0, acc[mi][nj][1] + b1};
            float2 v1 = {acc[mi][nj][2] + b0, acc[mi][nj][3] + b1};
            *(float2*)(C + (size_t)(r0 + mi * 16) * NOUT + col)     = v0;
            *(float2*)(C + (size_t)(r0 + mi * 16 + 8) * NOUT + col) = v1;
        }
    }
}

// ---------------------------------------------------------------------------
// Fused log_px + forward chain. 16 lanes/batch, 2 batches/warp. (Unchanged.)
// ---------------------------------------------------------------------------
__global__ void __launch_bounds__(128) chain_kernel(
    const float* __restrict__ x, const float* __restrict__ theta,
    const float* __restrict__ ulpa, float* __restrict__ out)
{
    __shared__ float s_lpa[255 * 4];
    for (int d = threadIdx.x; d < 255; d += 128) {
        float u0 = ulpa[d * 4 + 0], u1 = ulpa[d * 4 + 1];
        float u2 = ulpa[d * 4 + 2], u3 = ulpa[d * 4 + 3];
        float m = fmaxf(fmaxf(u0, u1), fmaxf(u2, u3));
        float s = expf(u0 - m) + expf(u1 - m) + expf(u2 - m) + expf(u3 - m);
        float lse = m + logf(s);
        s_lpa[d * 4 + 0] = u0 - lse;
        s_lpa[d * 4 + 1] = u1 - lse;
        s_lpa[d * 4 + 2] = u2 - lse;
        s_lpa[d * 4 + 3] = u3 - lse;
    }
    __syncthreads();

    const int lane = threadIdx.x & 31;
    const int wid  = threadIdx.x >> 5;
    const int half = lane >> 4;
    const int l    = lane & 15;
    const int i    = l >> 2, j = l & 3;
    const int b    = (blockIdx.x * 4 + wid) * 2 + half;

    const unsigned FULL = 0xffffffffu;
    const float NL = -0.91893853320467274178f;

    const float* th = theta + (size_t)b * NOUT;
    const float* xb = x + (size_t)b * DIN;

    float carry;
    {
        float mu = __ldg(th + l), ls = __ldg(th + 16 + l);
        float xd = __ldg(xb);
        float sd = __expf(ls) + 0.01f;
        float z = __fdividef(xd - mu, sd);
        float lp = fmaf(-0.5f * z, z, NL) - __logf(sd);
        float v = lp + s_lpa[j];
        carry = __shfl_sync(FULL, v, half * 16 + j);
    }
    float mu = __ldg(th + 32 + l), ls = __ldg(th + 48 + l);
    float xd = __ldg(xb + 1);
    #pragma unroll 1
    for (int d = 1; d < 255; d++) {
        float nmu = __ldg(th + (d + 1) * 32 + l);
        float nls = __ldg(th + (d + 1) * 32 + 16 + l);
        float nxd = __ldg(xb + d + 1);
        float sd = __expf(ls) + 0.01f;
        float z = __fdividef(xd - mu, sd);
        float lp = fmaf(-0.5f * z, z, NL) - __logf(sd);
        float ci = __shfl_sync(FULL, carry, half * 16 + i);
        float tv = ci + lp + s_lpa[d * 4 + j];
        float m = fmaxf(tv, __shfl_xor_sync(FULL, tv, 4));
        m = fmaxf(m, __shfl_xor_sync(FULL, m, 8));
        float s = __expf(tv - m);
        s += __shfl_xor_sync(FULL, s, 4);
        s += __shfl_xor_sync(FULL, s, 8);
        carry = m + __logf(s);
        mu = nmu; ls = nls; xd = nxd;
    }
    {
        float sd = __expf(ls) + 0.01f;
        float z = __fdividef(xd - mu, sd);
        float lp = fmaf(-0.5f * z, z, NL) - __logf(sd);
        float ci = __shfl_sync(FULL, carry, half * 16 + i);
        float tv = (j == 0) ? (ci + lp) : -1e30f;
        float m = fmaxf(tv, __shfl_xor_sync(FULL, tv, 1));
        m = fmaxf(m, __shfl_xor_sync(FULL, m, 2));
        m = fmaxf(m, __shfl_xor_sync(FULL, m, 4));
        m = fmaxf(m, __shfl_xor_sync(FULL, m, 8));
        float s = __expf(tv - m);
        s += __shfl_xor_sync(FULL, s, 1);
        s += __shfl_xor_sync(FULL, s, 2);
        s += __shfl_xor_sync(FULL, s, 4);
        s += __shfl_xor_sync(FULL, s, 8);
        if (l == 0) out[b] = m + __logf(s);
    }
}

// ---------------------------------------------------------------------------
// kernel_launch
// ---------------------------------------------------------------------------
extern "C" void kernel_launch(void* const* d_in, const int* in_sizes, int n_in,
                              void* d_out, int out_size)
{
    const float* x    = (const float*)d_in[0];
    const float* W0   = (const float*)d_in[1];
    const float* b0   = (const float*)d_in[2];
    const float* W1   = (const float*)d_in[3];
    const float* b1   = (const float*)d_in[4];
    const float* W2   = (const float*)d_in[5];
    const float* b2   = (const float*)d_in[6];
    const float* Wout = (const float*)d_in[7];
    const float* bout = (const float*)d_in[8];
    const float* ulpa = (const float*)d_in[9];

    float* out   = (float*)d_out;
    float* theta = out + BATCH;

    bf16 *xhi, *xlo, *w0hi, *w0lo, *w1hi, *w1lo, *w2hi, *w2lo;
    bf16 *h0hi, *h0lo, *h1hi, *h1lo, *h2hi, *h2lo, *whi, *wlo;
    cudaGetSymbolAddress((void**)&xhi, g_xhi);   cudaGetSymbolAddress((void**)&xlo, g_xlo);
    cudaGetSymbolAddress((void**)&w0hi, g_w0hi); cudaGetSymbolAddress((void**)&w0lo, g_w0lo);
    cudaGetSymbolAddress((void**)&w1hi, g_w1hi); cudaGetSymbolAddress((void**)&w1lo, g_w1lo);
    cudaGetSymbolAddress((void**)&w2hi, g_w2hi); cudaGetSymbolAddress((void**)&w2lo, g_w2lo);
    cudaGetSymbolAddress((void**)&h0hi, g_h0hi); cudaGetSymbolAddress((void**)&h0lo, g_h0lo);
    cudaGetSymbolAddress((void**)&h1hi, g_h1hi); cudaGetSymbolAddress((void**)&h1lo, g_h1lo);
    cudaGetSymbolAddress((void**)&h2hi, g_h2hi); cudaGetSymbolAddress((void**)&h2lo, g_h2lo);
    cudaGetSymbolAddress((void**)&whi, g_whi);   cudaGetSymbolAddress((void**)&wlo, g_wlo);

    cudaFuncSetAttribute(gemm_mma_kernel,
                         cudaFuncAttributeMaxDynamicSharedMemorySize, 98304);
    cudaFuncSetAttribute(layer_kernel<DIN, 0>,
                         cudaFuncAttributeMaxDynamicSharedMemorySize, 36864);
    cudaFuncSetAttribute(layer_kernel<HID, 1>,
                         cudaFuncAttributeMaxDynamicSharedMemorySize, 36864);

    split_wout_kernel<<<NOUT * HID / 4 / 256, 256>>>(Wout);
    prep_kernel<<<896, 256>>>(x, W0, W1, W2);

    layer_kernel<DIN, 0><<<dim3(HID / 64, BATCH / 32), 256, 36864>>>(
        xhi, xlo, w0hi, w0lo, b0, h0hi, h0lo);
    layer_kernel<HID, 1><<<dim3(HID / 64, BATCH / 32), 256, 36864>>>(
        h0hi, h0lo, w1hi, w1lo, b1, h1hi, h1lo);
    layer_kernel<HID, 1><<<dim3(HID / 64, BATCH / 32), 256, 36864>>>(
        h1hi, h1lo, w2hi, w2lo, b2, h2hi, h2lo);

    gemm_mma_kernel<<<dim3(NOUT / 128, BATCH / 128), 256, 98304>>>(
        h2hi, h2lo, whi, wlo, bout, theta);

    chain_kernel<<<BATCH / 8, 128>>>(x, theta, ulpa, out);
}

// round 11
// speedup vs baseline: 1.5802x; 1.4105x over previous
#include <cuda_runtime.h>
#include <cuda_bf16.h>
#include <math.h>
#include <stdint.h>

#define BATCH 1024
#define DIN   256
#define HID   512
#define KOUT  32
#define NOUT  (DIN * KOUT)  // 8192

typedef __nv_bfloat16 bf16;

// Scratch (allocation-free rule -> __device__ globals)
__device__ bf16 g_xhi[BATCH * DIN],  g_xlo[BATCH * DIN];
__device__ bf16 g_w0hi[HID * DIN],   g_w0lo[HID * DIN];
__device__ bf16 g_w1hi[HID * HID],   g_w1lo[HID * HID];
__device__ bf16 g_w2hi[HID * HID],   g_w2lo[HID * HID];
__device__ bf16 g_h0hi[BATCH * HID], g_h0lo[BATCH * HID];
__device__ bf16 g_h1hi[BATCH * HID], g_h1lo[BATCH * HID];
__device__ bf16 g_h2hi[BATCH * HID], g_h2lo[BATCH * HID];
__device__ bf16 g_whi[NOUT * HID],   g_wlo[NOUT * HID];

// ---------------------------------------------------------------------------
// PTX helpers (sm_80-baseline: ldmatrix / mma.sync / cp.async — tcgen05 is
// rejected by this toolchain's compute_103 stage; IMMA k32 measured 2x cost)
// ---------------------------------------------------------------------------
__device__ __forceinline__ uint32_t smem_u32(const void* p) {
    uint32_t a;
    asm("{ .reg .u64 t; cvta.to.shared.u64 t, %1; cvt.u32.u64 %0, t; }" : "=r"(a) : "l"(p));
    return a;
}
__device__ __forceinline__ void ldm_x4(uint32_t* r, uint32_t addr) {
    asm volatile("ldmatrix.sync.aligned.m8n8.x4.shared.b16 {%0,%1,%2,%3}, [%4];"
                 : "=r"(r[0]), "=r"(r[1]), "=r"(r[2]), "=r"(r[3]) : "r"(addr));
}
__device__ __forceinline__ void mma_bf16(float* d, const uint32_t* a, const uint32_t* b) {
    asm volatile("mma.sync.aligned.m16n8k16.row.col.f32.bf16.bf16.f32 "
                 "{%0,%1,%2,%3}, {%4,%5,%6,%7}, {%8,%9}, {%0,%1,%2,%3};"
                 : "+f"(d[0]), "+f"(d[1]), "+f"(d[2]), "+f"(d[3])
                 : "r"(a[0]), "r"(a[1]), "r"(a[2]), "r"(a[3]), "r"(b[0]), "r"(b[1]));
}
__device__ __forceinline__ void cp16(uint32_t dst, const void* src) {
    asm volatile("cp.async.cg.shared.global [%0], [%1], 16;" :: "r"(dst), "l"(src) : "memory");
}
__device__ __forceinline__ void cp_commit() {
    asm volatile("cp.async.commit_group;" ::: "memory");
}
template<int N> __device__ __forceinline__ void cp_wait() {
    asm volatile("cp.async.wait_group %0;" :: "n"(N) : "memory");
}
__device__ __forceinline__ void split2(float v, bf16& h, bf16& l) {
    h = __float2bfloat16(v);
    l = __float2bfloat16(v - __bfloat162float(h));
}
// min of (k % 255) over k in [a, a+32)
__device__ __forceinline__ int minmod255(int a) {
    return ((a + 31) / 255 > a / 255) ? 0 : (a % 255);
}

// ---------------------------------------------------------------------------
// Prep: split x, W0, W1, W2 into bf16 hi/lo with masks folded in.
// ---------------------------------------------------------------------------
__global__ void __launch_bounds__(256) prep_kernel(
    const float* __restrict__ x,  const float* __restrict__ W0,
    const float* __restrict__ W1, const float* __restrict__ W2)
{
    int t = blockIdx.x * 256 + threadIdx.x;
    const float* src; bf16 *hi, *lo;
    int mode, ksh, base;
    if (t < 65536)       { src = x;  hi = g_xhi;  lo = g_xlo;  mode = -1; ksh = 8; base = t * 4; }
    else if (t < 98304)  { src = W0; hi = g_w0hi; lo = g_w0lo; mode = 0;  ksh = 8; base = (t - 65536) * 4; }
    else if (t < 163840) { src = W1; hi = g_w1hi; lo = g_w1lo; mode = 1;  ksh = 9; base = (t - 98304) * 4; }
    else                 { src = W2; hi = g_w2hi; lo = g_w2lo; mode = 1;  ksh = 9; base = (t - 163840) * 4; }

    float4 v4 = *(const float4*)(src + base);
    float vv[4] = {v4.x, v4.y, v4.z, v4.w};
    int n = base >> ksh;
    int k0 = base & ((1 << ksh) - 1);
    int nd = n % 255;
    bf16 h[4], l[4];
    #pragma unroll
    for (int q = 0; q < 4; q++) {
        float v = vv[q];
        int k = k0 + q;
        if (mode == 0 && !(nd >= k)) v = 0.0f;
        if (mode == 1 && !(nd >= (k % 255))) v = 0.0f;
        split2(v, h[q], l[q]);
    }
    *(uint2*)(hi + base) = *(uint2*)h;
    *(uint2*)(lo + base) = *(uint2*)l;
}

// Wout split with output mask (MODE 2)
__global__ void __launch_bounds__(256) split_wout_kernel(const float* __restrict__ W)
{
    int idx = blockIdx.x * 256 + threadIdx.x;
    int base = idx * 4;
    int n = base >> 9, k0 = base & 511;
    int od = (n >> 5) - 1;
    float4 w4 = *(const float4*)(W + base);
    float wv[4] = {w4.x, w4.y, w4.z, w4.w};
    bf16 h[4], l[4];
    #pragma unroll
    for (int q = 0; q < 4; q++) {
        float v = (od >= ((k0 + q) % 255)) ? wv[q] : 0.0f;
        split2(v, h[q], l[q]);
    }
    *(uint2*)(g_whi + base) = *(uint2*)h;
    *(uint2*)(g_wlo + base) = *(uint2*)l;
}

// ---------------------------------------------------------------------------
// Small-layer HMMA kernel: C = relu(A @ W^T + b), split epilogue -> Chi/Clo.
// Tile 32m x 64n, BK=32, 128 threads (4 warps all in n; warp = 32m x 16n).
// grid = (N/64, M/32) = 256 CTAs. 4-stage cp.async; dead K-chunks skipped.
// (R7 champion config; only change: S=3 -> S=4.)
// ---------------------------------------------------------------------------
template<int K, int MODE>
__global__ void __launch_bounds__(128) layer_kernel(
    const bf16* __restrict__ Ahi, const bf16* __restrict__ Alo,
    const bf16* __restrict__ Whi, const bf16* __restrict__ Wlo,
    const float* __restrict__ bias,
    bf16* __restrict__ Chi, bf16* __restrict__ Clo)
{
    constexpr int NC = K / 32;
    constexpr int S = 4;
    constexpr uint32_t STG = 12288;  // 12KB per stage
    extern __shared__ bf16 smL[];
    const int tid = threadIdx.x, lane = tid & 31, wn = tid >> 5;
    const int bm = blockIdx.y * 32;
    const int bn = ((int)gridDim.x - 1 - (int)blockIdx.x) * 64;
    const uint32_t sb = smem_u32(smL);

    // max of (bn+r)%255 over the 64 N-rows (analytic)
    const int md = (bn / 255 == (bn + 63) / 255) ? ((bn + 63) % 255) : 254;

    int act[NC]; int na = 0;
    #pragma unroll
    for (int kc = 0; kc < NC; kc++) {
        int mm = (MODE == 0) ? (32 * kc) : minmod255(32 * kc);
        if (md >= mm) act[na++] = kc;
    }

    auto load_stage = [&](int s, int kc) {
        uint32_t stg = sb + (uint32_t)s * STG;
        {   // A tiles: 32 rows x 32 cols (64B/row), hi+lo
            int r = tid >> 2, c = tid & 3;
            uint32_t dsw = (uint32_t)(r * 64 + ((c ^ ((r >> 1) & 3)) << 4));
            size_t asrc = (size_t)(bm + r) * K + kc * 32 + c * 8;
            cp16(stg + dsw,         Ahi + asrc);
            cp16(stg + 2048u + dsw, Alo + asrc);
        }
        #pragma unroll
        for (int i = 0; i < 2; i++) {  // W tiles: 64 rows, hi+lo
            int idx = tid + i * 128;
            int r = idx >> 2, c = idx & 3;
            uint32_t dsw = (uint32_t)(r * 64 + ((c ^ ((r >> 1) & 3)) << 4));
            size_t wsrc = (size_t)(bn + r) * K + kc * 32 + c * 8;
            cp16(stg + 4096u + dsw, Whi + wsrc);
            cp16(stg + 8192u + dsw, Wlo + wsrc);
        }
    };

    int raby[2], swa[2];
    #pragma unroll
    for (int mi = 0; mi < 2; mi++) {
        int r = mi * 16 + (lane & 15);
        raby[mi] = r * 64;
        swa[mi] = (r >> 1) & 3;
    }
    const int hiA = lane >> 4;
    const int nloc = wn * 16 + (((lane >> 3) >> 1) << 3) + (lane & 7);
    const int rbby = nloc * 64, swb = (nloc >> 1) & 3, cbB = (lane >> 3) & 1;

    float acc[2][2][4];
    #pragma unroll
    for (int a = 0; a < 2; a++)
        #pragma unroll
        for (int bq = 0; bq < 2; bq++)
            #pragma unroll
            for (int q = 0; q < 4; q++) acc[a][bq][q] = 0.0f;

    #pragma unroll
    for (int s = 0; s < S - 1; s++) { if (s < na) load_stage(s, act[s]); cp_commit(); }

    #pragma unroll 1
    for (int ii = 0; ii < na; ii++) {
        cp_wait<S - 2>();
        __syncthreads();
        int ld = ii + S - 1;
        if (ld < na) load_stage(ld % S, act[ld]);
        cp_commit();

        uint32_t stg = sb + (uint32_t)(ii % S) * STG;
        #pragma unroll
        for (int k16 = 0; k16 < 2; k16++) {
            uint32_t a0[2][4], a1[2][4];
            #pragma unroll
            for (int mi = 0; mi < 2; mi++) {
                uint32_t off = (uint32_t)(raby[mi] + ((((k16 << 1) | hiA) ^ swa[mi]) << 4));
                ldm_x4(a0[mi], stg + off);
                ldm_x4(a1[mi], stg + 2048u + off);
            }
            uint32_t boff = (uint32_t)(rbby + ((((k16 << 1) | cbB) ^ swb) << 4));
            uint32_t bh[4];
            ldm_x4(bh, stg + 4096u + boff);
            #pragma unroll
            for (int mi = 0; mi < 2; mi++) {
                mma_bf16(acc[mi][0], a0[mi], &bh[0]);
                mma_bf16(acc[mi][1], a0[mi], &bh[2]);
                mma_bf16(acc[mi][0], a1[mi], &bh[0]);
                mma_bf16(acc[mi][1], a1[mi], &bh[2]);
            }
            uint32_t bl[4];
            ldm_x4(bl, stg + 8192u + boff);
            #pragma unroll
            for (int mi = 0; mi < 2; mi++) {
                mma_bf16(acc[mi][0], a0[mi], &bl[0]);
                mma_bf16(acc[mi][1], a0[mi], &bl[2]);
            }
        }
    }
    cp_wait<0>();

    const int r0 = bm + (lane >> 2);
    const int c0 = bn + wn * 16 + (lane & 3) * 2;
    #pragma unroll
    for (int mi = 0; mi < 2; mi++) {
        #pragma unroll
        for (int nj = 0; nj < 2; nj++) {
            int c = c0 + nj * 8;
            float b0 = bias[c], b1 = bias[c + 1];
            float v00 = fmaxf(acc[mi][nj][0] + b0, 0.0f);
            float v01 = fmaxf(acc[mi][nj][1] + b1, 0.0f);
            float v10 = fmaxf(acc[mi][nj][2] + b0, 0.0f);
            float v11 = fmaxf(acc[mi][nj][3] + b1, 0.0f);
            bf16 h0, l0, h1, l1;
            split2(v00, h0, l0); split2(v01, h1, l1);
            size_t o0 = (size_t)(r0 + mi * 16) * HID + c;
            *(__nv_bfloat162*)(Chi + o0) = __halves2bfloat162(h0, h1);
            *(__nv_bfloat162*)(Clo + o0) = __halves2bfloat162(l0, l1);
            split2(v10, h0, l0); split2(v11, h1, l1);
            size_t o1 = (size_t)(r0 + mi * 16 + 8) * HID + c;
            *(__nv_bfloat162*)(Chi + o1) = __halves2bfloat162(h0, h1);
            *(__nv_bfloat162*)(Clo + o1) = __halves2bfloat162(l0, l1);
        }
    }
}

// ---------------------------------------------------------------------------
// Big HMMA GEMM: theta[1024,8192] = h2 @ Wout^T + bout (3-term split).
// Tile 128x128, BK=32, 256 threads, 3-stage pipeline, chunk-skip by mask,
// heavy tiles first (reversed bid). (EXACT R7 version — proven 176.9us.)
// ---------------------------------------------------------------------------
__global__ void __launch_bounds__(256) gemm_mma_kernel(
    const bf16* __restrict__ Ahi, const bf16* __restrict__ Alo,
    const bf16* __restrict__ Whi, const bf16* __restrict__ Wlo,
    const float* __restrict__ bias, float* __restrict__ C)
{
    constexpr int NC = HID / 32;   // 16
    constexpr int S = 3;
    extern __shared__ bf16 smd[];
    const int tid = threadIdx.x, lane = tid & 31, wrp = tid >> 5;
    const int wm = wrp >> 2, wn = wrp & 3;
    const int bm = blockIdx.y * 128;
    const int bn = ((int)gridDim.x - 1 - (int)blockIdx.x) * 128;
    const uint32_t sb = smem_u32(smd);

    const int T = (bn >> 5) + 2;
    int act[NC]; int na = 0;
    #pragma unroll
    for (int kc = 0; kc < NC; kc++)
        if (minmod255(32 * kc) <= T) act[na++] = kc;

    auto load_stage = [&](int s, int kc) {
        uint32_t stg = sb + (uint32_t)s * 32768u;
        #pragma unroll
        for (int i = 0; i < 2; i++) {
            int idx = tid + i * 256;
            int r = idx >> 2, c = idx & 3;
            uint32_t dsw = (uint32_t)(r * 64 + ((c ^ ((r >> 1) & 3)) << 4));
            size_t asrc = (size_t)(bm + r) * HID + kc * 32 + c * 8;
            size_t wsrc = (size_t)(bn + r) * HID + kc * 32 + c * 8;
            cp16(stg + dsw,          Ahi + asrc);
            cp16(stg + 8192u + dsw,  Alo + asrc);
            cp16(stg + 16384u + dsw, Whi + wsrc);
            cp16(stg + 24576u + dsw, Wlo + wsrc);
        }
    };

    int raby[4], swa[4];
    #pragma unroll
    for (int mi = 0; mi < 4; mi++) {
        int r = wm * 64 + mi * 16 + (lane & 15);
        raby[mi] = r * 64;
        swa[mi] = (r >> 1) & 3;
    }
    const int hiA = lane >> 4;
    int rbby[2], swb[2];
    #pragma unroll
    for (int p = 0; p < 2; p++) {
        int n = wn * 32 + p * 16 + (((lane >> 3) >> 1) << 3) + (lane & 7);
        rbby[p] = n * 64;
        swb[p] = (n >> 1) & 3;
    }
    const int cbB = (lane >> 3) & 1;

    float acc[4][4][4];
    #pragma unroll
    for (int a = 0; a < 4; a++)
        #pragma unroll
        for (int bq = 0; bq < 4; bq++)
            #pragma unroll
            for (int q = 0; q < 4; q++) acc[a][bq][q] = 0.0f;

    #pragma unroll
    for (int s = 0; s < S - 1; s++) { if (s < na) load_stage(s, act[s]); cp_commit(); }

    #pragma unroll 1
    for (int ii = 0; ii < na; ii++) {
        cp_wait<S - 2>();
        __syncthreads();
        int ld = ii + S - 1;
        if (ld < na) load_stage(ld % S, act[ld]);
        cp_commit();

        uint32_t stg = sb + (uint32_t)(ii % S) * 32768u;
        #pragma unroll
        for (int k16 = 0; k16 < 2; k16++) {
            uint32_t a0[4][4], a1[4][4];
            #pragma unroll
            for (int mi = 0; mi < 4; mi++) {
                uint32_t off = (uint32_t)(raby[mi] + ((((k16 << 1) | hiA) ^ swa[mi]) << 4));
                ldm_x4(a0[mi], stg + off);
                ldm_x4(a1[mi], stg + 8192u + off);
            }
            #pragma unroll
            for (int p = 0; p < 2; p++) {
                uint32_t boff = (uint32_t)(rbby[p] + ((((k16 << 1) | cbB) ^ swb[p]) << 4));
                uint32_t bh[4];
                ldm_x4(bh, stg + 16384u + boff);
                #pragma unroll
                for (int mi = 0; mi < 4; mi++) {
                    mma_bf16(acc[mi][p * 2 + 0], a0[mi], &bh[0]);
                    mma_bf16(acc[mi][p * 2 + 1], a0[mi], &bh[2]);
                    mma_bf16(acc[mi][p * 2 + 0], a1[mi], &bh[0]);
                    mma_bf16(acc[mi][p * 2 + 1], a1[mi], &bh[2]);
                }
                uint32_t bl[4];
                ldm_x4(bl, stg + 24576u + boff);
                #pragma unroll
                for (int mi = 0; mi < 4; mi++) {
                    mma_bf16(acc[mi][p * 2 + 0], a0[mi], &bl[0]);
                    mma_bf16(acc[mi][p * 2 + 1], a0[mi], &bl[2]);
                }
            }
        }
    }
    cp_wait<0>();

    const int r0 = bm + wm * 64 + (lane >> 2);
    const int cbase = bn + wn * 32 + (lane & 3) * 2;
    #pragma unroll
    for (int mi = 0; mi < 4; mi++) {
        #pragma unroll
        for (int nj = 0; nj < 4; nj++) {
            int col = cbase + nj * 8;
            float b0 = bias[col], b1 = bias[col + 1];
            float2 v0 = {acc[mi][nj][0] + b0, acc[mi][nj][1] + b1};
            float2 v1 = {acc[mi][nj][2] + b0, acc[mi][nj][3] + b1};
            *(float2*)(C + (size_t)(r0 + mi * 16) * NOUT + col)     = v0;
            *(float2*)(C + (size_t)(r0 + mi * 16 + 8) * NOUT + col) = v1;
        }
    }
}

// ---------------------------------------------------------------------------
// Fused log_px + forward chain. 16 lanes/batch, 2 batches/warp. (Unchanged.)
// ---------------------------------------------------------------------------
__global__ void __launch_bounds__(128) chain_kernel(
    const float* __restrict__ x, const float* __restrict__ theta,
    const float* __restrict__ ulpa, float* __restrict__ out)
{
    __shared__ float s_lpa[255 * 4];
    for (int d = threadIdx.x; d < 255; d += 128) {
        float u0 = ulpa[d * 4 + 0], u1 = ulpa[d * 4 + 1];
        float u2 = ulpa[d * 4 + 2], u3 = ulpa[d * 4 + 3];
        float m = fmaxf(fmaxf(u0, u1), fmaxf(u2, u3));
        float s = expf(u0 - m) + expf(u1 - m) + expf(u2 - m) + expf(u3 - m);
        float lse = m + logf(s);
        s_lpa[d * 4 + 0] = u0 - lse;
        s_lpa[d * 4 + 1] = u1 - lse;
        s_lpa[d * 4 + 2] = u2 - lse;
        s_lpa[d * 4 + 3] = u3 - lse;
    }
    __syncthreads();

    const int lane = threadIdx.x & 31;
    const int wid  = threadIdx.x >> 5;
    const int half = lane >> 4;
    const int l    = lane & 15;
    const int i    = l >> 2, j = l & 3;
    const int b    = (blockIdx.x * 4 + wid) * 2 + half;

    const unsigned FULL = 0xffffffffu;
    const float NL = -0.91893853320467274178f;

    const float* th = theta + (size_t)b * NOUT;
    const float* xb = x + (size_t)b * DIN;

    float carry;
    {
        float mu = __ldg(th + l), ls = __ldg(th + 16 + l);
        float xd = __ldg(xb);
        float sd = __expf(ls) + 0.01f;
        float z = __fdividef(xd - mu, sd);
        float lp = fmaf(-0.5f * z, z, NL) - __logf(sd);
        float v = lp + s_lpa[j];
        carry = __shfl_sync(FULL, v, half * 16 + j);
    }
    float mu = __ldg(th + 32 + l), ls = __ldg(th + 48 + l);
    float xd = __ldg(xb + 1);
    #pragma unroll 1
    for (int d = 1; d < 255; d++) {
        float nmu = __ldg(th + (d + 1) * 32 + l);
        float nls = __ldg(th + (d + 1) * 32 + 16 + l);
        float nxd = __ldg(xb + d + 1);
        float sd = __expf(ls) + 0.01f;
        float z = __fdividef(xd - mu, sd);
        float lp = fmaf(-0.5f * z, z, NL) - __logf(sd);
        float ci = __shfl_sync(FULL, carry, half * 16 + i);
        float tv = ci + lp + s_lpa[d * 4 + j];
        float m = fmaxf(tv, __shfl_xor_sync(FULL, tv, 4));
        m = fmaxf(m, __shfl_xor_sync(FULL, m, 8));
        float s = __expf(tv - m);
        s += __shfl_xor_sync(FULL, s, 4);
        s += __shfl_xor_sync(FULL, s, 8);
        carry = m + __logf(s);
        mu = nmu; ls = nls; xd = nxd;
    }
    {
        float sd = __expf(ls) + 0.01f;
        float z = __fdividef(xd - mu, sd);
        float lp = fmaf(-0.5f * z, z, NL) - __logf(sd);
        float ci = __shfl_sync(FULL, carry, half * 16 + i);
        float tv = (j == 0) ? (ci + lp) : -1e30f;
        float m = fmaxf(tv, __shfl_xor_sync(FULL, tv, 1));
        m = fmaxf(m, __shfl_xor_sync(FULL, m, 2));
        m = fmaxf(m, __shfl_xor_sync(FULL, m, 4));
        m = fmaxf(m, __shfl_xor_sync(FULL, m, 8));
        float s = __expf(tv - m);
        s += __shfl_xor_sync(FULL, s, 1);
        s += __shfl_xor_sync(FULL, s, 2);
        s += __shfl_xor_sync(FULL, s, 4);
        s += __shfl_xor_sync(FULL, s, 8);
        if (l == 0) out[b] = m + __logf(s);
    }
}

// ---------------------------------------------------------------------------
// kernel_launch
// ---------------------------------------------------------------------------
extern "C" void kernel_launch(void* const* d_in, const int* in_sizes, int n_in,
                              void* d_out, int out_size)
{
    const float* x    = (const float*)d_in[0];
    const float* W0   = (const float*)d_in[1];
    const float* b0   = (const float*)d_in[2];
    const float* W1   = (const float*)d_in[3];
    const float* b1   = (const float*)d_in[4];
    const float* W2   = (const float*)d_in[5];
    const float* b2   = (const float*)d_in[6];
    const float* Wout = (const float*)d_in[7];
    const float* bout = (const float*)d_in[8];
    const float* ulpa = (const float*)d_in[9];

    float* out   = (float*)d_out;
    float* theta = out + BATCH;

    bf16 *xhi, *xlo, *w0hi, *w0lo, *w1hi, *w1lo, *w2hi, *w2lo;
    bf16 *h0hi, *h0lo, *h1hi, *h1lo, *h2hi, *h2lo, *whi, *wlo;
    cudaGetSymbolAddress((void**)&xhi, g_xhi);   cudaGetSymbolAddress((void**)&xlo, g_xlo);
    cudaGetSymbolAddress((void**)&w0hi, g_w0hi); cudaGetSymbolAddress((void**)&w0lo, g_w0lo);
    cudaGetSymbolAddress((void**)&w1hi, g_w1hi); cudaGetSymbolAddress((void**)&w1lo, g_w1lo);
    cudaGetSymbolAddress((void**)&w2hi, g_w2hi); cudaGetSymbolAddress((void**)&w2lo, g_w2lo);
    cudaGetSymbolAddress((void**)&h0hi, g_h0hi); cudaGetSymbolAddress((void**)&h0lo, g_h0lo);
    cudaGetSymbolAddress((void**)&h1hi, g_h1hi); cudaGetSymbolAddress((void**)&h1lo, g_h1lo);
    cudaGetSymbolAddress((void**)&h2hi, g_h2hi); cudaGetSymbolAddress((void**)&h2lo, g_h2lo);
    cudaGetSymbolAddress((void**)&whi, g_whi);   cudaGetSymbolAddress((void**)&wlo, g_wlo);

    cudaFuncSetAttribute(gemm_mma_kernel,
                         cudaFuncAttributeMaxDynamicSharedMemorySize, 98304);
    cudaFuncSetAttribute(layer_kernel<DIN, 0>,
                         cudaFuncAttributeMaxDynamicSharedMemorySize, 49152);
    cudaFuncSetAttribute(layer_kernel<HID, 1>,
                         cudaFuncAttributeMaxDynamicSharedMemorySize, 49152);

    split_wout_kernel<<<NOUT * HID / 4 / 256, 256>>>(Wout);
    prep_kernel<<<896, 256>>>(x, W0, W1, W2);

    layer_kernel<DIN, 0><<<dim3(HID / 64, BATCH / 32), 128, 49152>>>(
        xhi, xlo, w0hi, w0lo, b0, h0hi, h0lo);
    layer_kernel<HID, 1><<<dim3(HID / 64, BATCH / 32), 128, 49152>>>(
        h0hi, h0lo, w1hi, w1lo, b1, h1hi, h1lo);
    layer_kernel<HID, 1><<<dim3(HID / 64, BATCH / 32), 128, 49152>>>(
        h1hi, h1lo, w2hi, w2lo, b2, h2hi, h2lo);

    gemm_mma_kernel<<<dim3(NOUT / 128, BATCH / 128), 256, 98304>>>(
        h2hi, h2lo, whi, wlo, bout, theta);

    chain_kernel<<<BATCH / 8, 128>>>(x, theta, ulpa, out);
}

// round 12
// speedup vs baseline: 1.5881x; 1.0050x over previous
#include <cuda_runtime.h>
#include <cuda_bf16.h>
#include <math.h>
#include <stdint.h>

#define BATCH 1024
#define DIN   256
#define HID   512
#define KOUT  32
#define NOUT  (DIN * KOUT)  // 8192

typedef __nv_bfloat16 bf16;

// Scratch (allocation-free rule -> __device__ globals)
__device__ bf16 g_xhi[BATCH * DIN],  g_xlo[BATCH * DIN];
__device__ bf16 g_w0hi[HID * DIN],   g_w0lo[HID * DIN];
__device__ bf16 g_w1hi[HID * HID],   g_w1lo[HID * HID];
__device__ bf16 g_w2hi[HID * HID],   g_w2lo[HID * HID];
__device__ bf16 g_h0hi[BATCH * HID], g_h0lo[BATCH * HID];
__device__ bf16 g_h1hi[BATCH * HID], g_h1lo[BATCH * HID];
__device__ bf16 g_h2hi[BATCH * HID], g_h2lo[BATCH * HID];
__device__ bf16 g_whi[NOUT * HID],   g_wlo[NOUT * HID];

// ---------------------------------------------------------------------------
// PTX helpers (sm_80-baseline: ldmatrix / mma.sync / cp.async — tcgen05 is
// rejected by this toolchain's compute_103 stage; IMMA k32 measured 2x cost)
// ---------------------------------------------------------------------------
__device__ __forceinline__ uint32_t smem_u32(const void* p) {
    uint32_t a;
    asm("{ .reg .u64 t; cvta.to.shared.u64 t, %1; cvt.u32.u64 %0, t; }" : "=r"(a) : "l"(p));
    return a;
}
__device__ __forceinline__ void ldm_x4(uint32_t* r, uint32_t addr) {
    asm volatile("ldmatrix.sync.aligned.m8n8.x4.shared.b16 {%0,%1,%2,%3}, [%4];"
                 : "=r"(r[0]), "=r"(r[1]), "=r"(r[2]), "=r"(r[3]) : "r"(addr));
}
__device__ __forceinline__ void mma_bf16(float* d, const uint32_t* a, const uint32_t* b) {
    asm volatile("mma.sync.aligned.m16n8k16.row.col.f32.bf16.bf16.f32 "
                 "{%0,%1,%2,%3}, {%4,%5,%6,%7}, {%8,%9}, {%0,%1,%2,%3};"
                 : "+f"(d[0]), "+f"(d[1]), "+f"(d[2]), "+f"(d[3])
                 : "r"(a[0]), "r"(a[1]), "r"(a[2]), "r"(a[3]), "r"(b[0]), "r"(b[1]));
}
__device__ __forceinline__ void cp16(uint32_t dst, const void* src) {
    asm volatile("cp.async.cg.shared.global [%0], [%1], 16;" :: "r"(dst), "l"(src) : "memory");
}
__device__ __forceinline__ void cp_commit() {
    asm volatile("cp.async.commit_group;" ::: "memory");
}
template<int N> __device__ __forceinline__ void cp_wait() {
    asm volatile("cp.async.wait_group %0;" :: "n"(N) : "memory");
}
__device__ __forceinline__ void split2(float v, bf16& h, bf16& l) {
    h = __float2bfloat16(v);
    l = __float2bfloat16(v - __bfloat162float(h));
}
// min of (k % 255) over k in [a, a+32)
__device__ __forceinline__ int minmod255(int a) {
    return ((a + 31) / 255 > a / 255) ? 0 : (a % 255);
}

// ---------------------------------------------------------------------------
// Prep: split x, W0, W1, W2 into bf16 hi/lo with masks folded in.
// ---------------------------------------------------------------------------
__global__ void __launch_bounds__(256) prep_kernel(
    const float* __restrict__ x,  const float* __restrict__ W0,
    const float* __restrict__ W1, const float* __restrict__ W2)
{
    int t = blockIdx.x * 256 + threadIdx.x;
    const float* src; bf16 *hi, *lo;
    int mode, ksh, base;
    if (t < 65536)       { src = x;  hi = g_xhi;  lo = g_xlo;  mode = -1; ksh = 8; base = t * 4; }
    else if (t < 98304)  { src = W0; hi = g_w0hi; lo = g_w0lo; mode = 0;  ksh = 8; base = (t - 65536) * 4; }
    else if (t < 163840) { src = W1; hi = g_w1hi; lo = g_w1lo; mode = 1;  ksh = 9; base = (t - 98304) * 4; }
    else                 { src = W2; hi = g_w2hi; lo = g_w2lo; mode = 1;  ksh = 9; base = (t - 163840) * 4; }

    float4 v4 = *(const float4*)(src + base);
    float vv[4] = {v4.x, v4.y, v4.z, v4.w};
    int n = base >> ksh;
    int k0 = base & ((1 << ksh) - 1);
    int nd = n % 255;
    bf16 h[4], l[4];
    #pragma unroll
    for (int q = 0; q < 4; q++) {
        float v = vv[q];
        int k = k0 + q;
        if (mode == 0 && !(nd >= k)) v = 0.0f;
        if (mode == 1 && !(nd >= (k % 255))) v = 0.0f;
        split2(v, h[q], l[q]);
    }
    *(uint2*)(hi + base) = *(uint2*)h;
    *(uint2*)(lo + base) = *(uint2*)l;
}

// Wout split with output mask (MODE 2)
__global__ void __launch_bounds__(256) split_wout_kernel(const float* __restrict__ W)
{
    int idx = blockIdx.x * 256 + threadIdx.x;
    int base = idx * 4;
    int n = base >> 9, k0 = base & 511;
    int od = (n >> 5) - 1;
    float4 w4 = *(const float4*)(W + base);
    float wv[4] = {w4.x, w4.y, w4.z, w4.w};
    bf16 h[4], l[4];
    #pragma unroll
    for (int q = 0; q < 4; q++) {
        float v = (od >= ((k0 + q) % 255)) ? wv[q] : 0.0f;
        split2(v, h[q], l[q]);
    }
    *(uint2*)(g_whi + base) = *(uint2*)h;
    *(uint2*)(g_wlo + base) = *(uint2*)l;
}

// ---------------------------------------------------------------------------
// Small-layer HMMA kernel: C = relu(A @ W^T + b), split epilogue -> Chi/Clo.
// Tile 32m x 64n, BK=32, 128 threads (4 warps all in n; warp = 32m x 16n).
// grid = (N/64, M/32) = 256 CTAs. 3-stage cp.async; dead K-chunks skipped.
// (EXACT R7 champion config.)
// ---------------------------------------------------------------------------
template<int K, int MODE>
__global__ void __launch_bounds__(128) layer_kernel(
    const bf16* __restrict__ Ahi, const bf16* __restrict__ Alo,
    const bf16* __restrict__ Whi, const bf16* __restrict__ Wlo,
    const float* __restrict__ bias,
    bf16* __restrict__ Chi, bf16* __restrict__ Clo)
{
    constexpr int NC = K / 32;
    constexpr int S = 3;
    constexpr uint32_t STG = 12288;  // 12KB per stage
    extern __shared__ bf16 smL[];
    const int tid = threadIdx.x, lane = tid & 31, wn = tid >> 5;
    const int bm = blockIdx.y * 32;
    const int bn = ((int)gridDim.x - 1 - (int)blockIdx.x) * 64;
    const uint32_t sb = smem_u32(smL);

    // max of (bn+r)%255 over the 64 N-rows (analytic)
    const int md = (bn / 255 == (bn + 63) / 255) ? ((bn + 63) % 255) : 254;

    int act[NC]; int na = 0;
    #pragma unroll
    for (int kc = 0; kc < NC; kc++) {
        int mm = (MODE == 0) ? (32 * kc) : minmod255(32 * kc);
        if (md >= mm) act[na++] = kc;
    }

    auto load_stage = [&](int s, int kc) {
        uint32_t stg = sb + (uint32_t)s * STG;
        {   // A tiles: 32 rows x 32 cols (64B/row), hi+lo
            int r = tid >> 2, c = tid & 3;
            uint32_t dsw = (uint32_t)(r * 64 + ((c ^ ((r >> 1) & 3)) << 4));
            size_t asrc = (size_t)(bm + r) * K + kc * 32 + c * 8;
            cp16(stg + dsw,         Ahi + asrc);
            cp16(stg + 2048u + dsw, Alo + asrc);
        }
        #pragma unroll
        for (int i = 0; i < 2; i++) {  // W tiles: 64 rows, hi+lo
            int idx = tid + i * 128;
            int r = idx >> 2, c = idx & 3;
            uint32_t dsw = (uint32_t)(r * 64 + ((c ^ ((r >> 1) & 3)) << 4));
            size_t wsrc = (size_t)(bn + r) * K + kc * 32 + c * 8;
            cp16(stg + 4096u + dsw, Whi + wsrc);
            cp16(stg + 8192u + dsw, Wlo + wsrc);
        }
    };

    int raby[2], swa[2];
    #pragma unroll
    for (int mi = 0; mi < 2; mi++) {
        int r = mi * 16 + (lane & 15);
        raby[mi] = r * 64;
        swa[mi] = (r >> 1) & 3;
    }
    const int hiA = lane >> 4;
    const int nloc = wn * 16 + (((lane >> 3) >> 1) << 3) + (lane & 7);
    const int rbby = nloc * 64, swb = (nloc >> 1) & 3, cbB = (lane >> 3) & 1;

    float acc[2][2][4];
    #pragma unroll
    for (int a = 0; a < 2; a++)
        #pragma unroll
        for (int bq = 0; bq < 2; bq++)
            #pragma unroll
            for (int q = 0; q < 4; q++) acc[a][bq][q] = 0.0f;

    #pragma unroll
    for (int s = 0; s < S - 1; s++) { if (s < na) load_stage(s, act[s]); cp_commit(); }

    #pragma unroll 1
    for (int ii = 0; ii < na; ii++) {
        cp_wait<S - 2>();
        __syncthreads();
        int ld = ii + S - 1;
        if (ld < na) load_stage(ld % S, act[ld]);
        cp_commit();

        uint32_t stg = sb + (uint32_t)(ii % S) * STG;
        #pragma unroll
        for (int k16 = 0; k16 < 2; k16++) {
            uint32_t a0[2][4], a1[2][4];
            #pragma unroll
            for (int mi = 0; mi < 2; mi++) {
                uint32_t off = (uint32_t)(raby[mi] + ((((k16 << 1) | hiA) ^ swa[mi]) << 4));
                ldm_x4(a0[mi], stg + off);
                ldm_x4(a1[mi], stg + 2048u + off);
            }
            uint32_t boff = (uint32_t)(rbby + ((((k16 << 1) | cbB) ^ swb) << 4));
            uint32_t bh[4];
            ldm_x4(bh, stg + 4096u + boff);
            #pragma unroll
            for (int mi = 0; mi < 2; mi++) {
                mma_bf16(acc[mi][0], a0[mi], &bh[0]);
                mma_bf16(acc[mi][1], a0[mi], &bh[2]);
                mma_bf16(acc[mi][0], a1[mi], &bh[0]);
                mma_bf16(acc[mi][1], a1[mi], &bh[2]);
            }
            uint32_t bl[4];
            ldm_x4(bl, stg + 8192u + boff);
            #pragma unroll
            for (int mi = 0; mi < 2; mi++) {
                mma_bf16(acc[mi][0], a0[mi], &bl[0]);
                mma_bf16(acc[mi][1], a0[mi], &bl[2]);
            }
        }
    }
    cp_wait<0>();

    const int r0 = bm + (lane >> 2);
    const int c0 = bn + wn * 16 + (lane & 3) * 2;
    #pragma unroll
    for (int mi = 0; mi < 2; mi++) {
        #pragma unroll
        for (int nj = 0; nj < 2; nj++) {
            int c = c0 + nj * 8;
            float b0 = bias[c], b1 = bias[c + 1];
            float v00 = fmaxf(acc[mi][nj][0] + b0, 0.0f);
            float v01 = fmaxf(acc[mi][nj][1] + b1, 0.0f);
            float v10 = fmaxf(acc[mi][nj][2] + b0, 0.0f);
            float v11 = fmaxf(acc[mi][nj][3] + b1, 0.0f);
            bf16 h0, l0, h1, l1;
            split2(v00, h0, l0); split2(v01, h1, l1);
            size_t o0 = (size_t)(r0 + mi * 16) * HID + c;
            *(__nv_bfloat162*)(Chi + o0) = __halves2bfloat162(h0, h1);
            *(__nv_bfloat162*)(Clo + o0) = __halves2bfloat162(l0, l1);
            split2(v10, h0, l0); split2(v11, h1, l1);
            size_t o1 = (size_t)(r0 + mi * 16 + 8) * HID + c;
            *(__nv_bfloat162*)(Chi + o1) = __halves2bfloat162(h0, h1);
            *(__nv_bfloat162*)(Clo + o1) = __halves2bfloat162(l0, l1);
        }
    }
}

// ---------------------------------------------------------------------------
// Big HMMA GEMM: theta[1024,8192] = h2 @ Wout^T + bout (3-term split).
// Tile 128x128, BK=32, 256 threads, 3-stage pipeline, chunk-skip by mask,
// heavy tiles first (reversed bid). (EXACT R7 version — proven 176.9us.)
// ---------------------------------------------------------------------------
__global__ void __launch_bounds__(256) gemm_mma_kernel(
    const bf16* __restrict__ Ahi, const bf16* __restrict__ Alo,
    const bf16* __restrict__ Whi, const bf16* __restrict__ Wlo,
    const float* __restrict__ bias, float* __restrict__ C)
{
    constexpr int NC = HID / 32;   // 16
    constexpr int S = 3;
    extern __shared__ bf16 smd[];
    const int tid = threadIdx.x, lane = tid & 31, wrp = tid >> 5;
    const int wm = wrp >> 2, wn = wrp & 3;
    const int bm = blockIdx.y * 128;
    const int bn = ((int)gridDim.x - 1 - (int)blockIdx.x) * 128;
    const uint32_t sb = smem_u32(smd);

    const int T = (bn >> 5) + 2;
    int act[NC]; int na = 0;
    #pragma unroll
    for (int kc = 0; kc < NC; kc++)
        if (minmod255(32 * kc) <= T) act[na++] = kc;

    auto load_stage = [&](int s, int kc) {
        uint32_t stg = sb + (uint32_t)s * 32768u;
        #pragma unroll
        for (int i = 0; i < 2; i++) {
            int idx = tid + i * 256;
            int r = idx >> 2, c = idx & 3;
            uint32_t dsw = (uint32_t)(r * 64 + ((c ^ ((r >> 1) & 3)) << 4));
            size_t asrc = (size_t)(bm + r) * HID + kc * 32 + c * 8;
            size_t wsrc = (size_t)(bn + r) * HID + kc * 32 + c * 8;
            cp16(stg + dsw,          Ahi + asrc);
            cp16(stg + 8192u + dsw,  Alo + asrc);
            cp16(stg + 16384u + dsw, Whi + wsrc);
            cp16(stg + 24576u + dsw, Wlo + wsrc);
        }
    };

    int raby[4], swa[4];
    #pragma unroll
    for (int mi = 0; mi < 4; mi++) {
        int r = wm * 64 + mi * 16 + (lane & 15);
        raby[mi] = r * 64;
        swa[mi] = (r >> 1) & 3;
    }
    const int hiA = lane >> 4;
    int rbby[2], swb[2];
    #pragma unroll
    for (int p = 0; p < 2; p++) {
        int n = wn * 32 + p * 16 + (((lane >> 3) >> 1) << 3) + (lane & 7);
        rbby[p] = n * 64;
        swb[p] = (n >> 1) & 3;
    }
    const int cbB = (lane >> 3) & 1;

    float acc[4][4][4];
    #pragma unroll
    for (int a = 0; a < 4; a++)
        #pragma unroll
        for (int bq = 0; bq < 4; bq++)
            #pragma unroll
            for (int q = 0; q < 4; q++) acc[a][bq][q] = 0.0f;

    #pragma unroll
    for (int s = 0; s < S - 1; s++) { if (s < na) load_stage(s, act[s]); cp_commit(); }

    #pragma unroll 1
    for (int ii = 0; ii < na; ii++) {
        cp_wait<S - 2>();
        __syncthreads();
        int ld = ii + S - 1;
        if (ld < na) load_stage(ld % S, act[ld]);
        cp_commit();

        uint32_t stg = sb + (uint32_t)(ii % S) * 32768u;
        #pragma unroll
        for (int k16 = 0; k16 < 2; k16++) {
            uint32_t a0[4][4], a1[4][4];
            #pragma unroll
            for (int mi = 0; mi < 4; mi++) {
                uint32_t off = (uint32_t)(raby[mi] + ((((k16 << 1) | hiA) ^ swa[mi]) << 4));
                ldm_x4(a0[mi], stg + off);
                ldm_x4(a1[mi], stg + 8192u + off);
            }
            #pragma unroll
            for (int p = 0; p < 2; p++) {
                uint32_t boff = (uint32_t)(rbby[p] + ((((k16 << 1) | cbB) ^ swb[p]) << 4));
                uint32_t bh[4];
                ldm_x4(bh, stg + 16384u + boff);
                #pragma unroll
                for (int mi = 0; mi < 4; mi++) {
                    mma_bf16(acc[mi][p * 2 + 0], a0[mi], &bh[0]);
                    mma_bf16(acc[mi][p * 2 + 1], a0[mi], &bh[2]);
                    mma_bf16(acc[mi][p * 2 + 0], a1[mi], &bh[0]);
                    mma_bf16(acc[mi][p * 2 + 1], a1[mi], &bh[2]);
                }
                uint32_t bl[4];
                ldm_x4(bl, stg + 24576u + boff);
                #pragma unroll
                for (int mi = 0; mi < 4; mi++) {
                    mma_bf16(acc[mi][p * 2 + 0], a0[mi], &bl[0]);
                    mma_bf16(acc[mi][p * 2 + 1], a0[mi], &bl[2]);
                }
            }
        }
    }
    cp_wait<0>();

    const int r0 = bm + wm * 64 + (lane >> 2);
    const int cbase = bn + wn * 32 + (lane & 3) * 2;
    #pragma unroll
    for (int mi = 0; mi < 4; mi++) {
        #pragma unroll
        for (int nj = 0; nj < 4; nj++) {
            int col = cbase + nj * 8;
            float b0 = bias[col], b1 = bias[col + 1];
            float2 v0 = {acc[mi][nj][0] + b0, acc[mi][nj][1] + b1};
            float2 v1 = {acc[mi][nj][2] + b0, acc[mi][nj][3] + b1};
            *(float2*)(C + (size_t)(r0 + mi * 16) * NOUT + col)     = v0;
            *(float2*)(C + (size_t)(r0 + mi * 16 + 8) * NOUT + col) = v1;
        }
    }
}

// ---------------------------------------------------------------------------
// Fused log_px + forward chain. 16 lanes/batch, 2 batches/warp. (Unchanged.)
// ---------------------------------------------------------------------------
__global__ void __launch_bounds__(128) chain_kernel(
    const float* __restrict__ x, const float* __restrict__ theta,
    const float* __restrict__ ulpa, float* __restrict__ out)
{
    __shared__ float s_lpa[255 * 4];
    for (int d = threadIdx.x; d < 255; d += 128) {
        float u0 = ulpa[d * 4 + 0], u1 = ulpa[d * 4 + 1];
        float u2 = ulpa[d * 4 + 2], u3 = ulpa[d * 4 + 3];
        float m = fmaxf(fmaxf(u0, u1), fmaxf(u2, u3));
        float s = expf(u0 - m) + expf(u1 - m) + expf(u2 - m) + expf(u3 - m);
        float lse = m + logf(s);
        s_lpa[d * 4 + 0] = u0 - lse;
        s_lpa[d * 4 + 1] = u1 - lse;
        s_lpa[d * 4 + 2] = u2 - lse;
        s_lpa[d * 4 + 3] = u3 - lse;
    }
    __syncthreads();

    const int lane = threadIdx.x & 31;
    const int wid  = threadIdx.x >> 5;
    const int half = lane >> 4;
    const int l    = lane & 15;
    const int i    = l >> 2, j = l & 3;
    const int b    = (blockIdx.x * 4 + wid) * 2 + half;

    const unsigned FULL = 0xffffffffu;
    const float NL = -0.91893853320467274178f;

    const float* th = theta + (size_t)b * NOUT;
    const float* xb = x + (size_t)b * DIN;

    float carry;
    {
        float mu = __ldg(th + l), ls = __ldg(th + 16 + l);
        float xd = __ldg(xb);
        float sd = __expf(ls) + 0.01f;
        float z = __fdividef(xd - mu, sd);
        float lp = fmaf(-0.5f * z, z, NL) - __logf(sd);
        float v = lp + s_lpa[j];
        carry = __shfl_sync(FULL, v, half * 16 + j);
    }
    float mu = __ldg(th + 32 + l), ls = __ldg(th + 48 + l);
    float xd = __ldg(xb + 1);
    #pragma unroll 1
    for (int d = 1; d < 255; d++) {
        float nmu = __ldg(th + (d + 1) * 32 + l);
        float nls = __ldg(th + (d + 1) * 32 + 16 + l);
        float nxd = __ldg(xb + d + 1);
        float sd = __expf(ls) + 0.01f;
        float z = __fdividef(xd - mu, sd);
        float lp = fmaf(-0.5f * z, z, NL) - __logf(sd);
        float ci = __shfl_sync(FULL, carry, half * 16 + i);
        float tv = ci + lp + s_lpa[d * 4 + j];
        float m = fmaxf(tv, __shfl_xor_sync(FULL, tv, 4));
        m = fmaxf(m, __shfl_xor_sync(FULL, m, 8));
        float s = __expf(tv - m);
        s += __shfl_xor_sync(FULL, s, 4);
        s += __shfl_xor_sync(FULL, s, 8);
        carry = m + __logf(s);
        mu = nmu; ls = nls; xd = nxd;
    }
    {
        float sd = __expf(ls) + 0.01f;
        float z = __fdividef(xd - mu, sd);
        float lp = fmaf(-0.5f * z, z, NL) - __logf(sd);
        float ci = __shfl_sync(FULL, carry, half * 16 + i);
        float tv = (j == 0) ? (ci + lp) : -1e30f;
        float m = fmaxf(tv, __shfl_xor_sync(FULL, tv, 1));
        m = fmaxf(m, __shfl_xor_sync(FULL, m, 2));
        m = fmaxf(m, __shfl_xor_sync(FULL, m, 4));
        m = fmaxf(m, __shfl_xor_sync(FULL, m, 8));
        float s = __expf(tv - m);
        s += __shfl_xor_sync(FULL, s, 1);
        s += __shfl_xor_sync(FULL, s, 2);
        s += __shfl_xor_sync(FULL, s, 4);
        s += __shfl_xor_sync(FULL, s, 8);
        if (l == 0) out[b] = m + __logf(s);
    }
}

// ---------------------------------------------------------------------------
// kernel_launch: split_wout forked onto a non-blocking stream, joined
// before the gemm. Streams/events are host objects created on first call
// (the non-captured correctness run) and reused during capture.
// ---------------------------------------------------------------------------
extern "C" void kernel_launch(void* const* d_in, const int* in_sizes, int n_in,
                              void* d_out, int out_size)
{
    const float* x    = (const float*)d_in[0];
    const float* W0   = (const float*)d_in[1];
    const float* b0   = (const float*)d_in[2];
    const float* W1   = (const float*)d_in[3];
    const float* b1   = (const float*)d_in[4];
    const float* W2   = (const float*)d_in[5];
    const float* b2   = (const float*)d_in[6];
    const float* Wout = (const float*)d_in[7];
    const float* bout = (const float*)d_in[8];
    const float* ulpa = (const float*)d_in[9];

    float* out   = (float*)d_out;
    float* theta = out + BATCH;

    bf16 *xhi, *xlo, *w0hi, *w0lo, *w1hi, *w1lo, *w2hi, *w2lo;
    bf16 *h0hi, *h0lo, *h1hi, *h1lo, *h2hi, *h2lo, *whi, *wlo;
    cudaGetSymbolAddress((void**)&xhi, g_xhi);   cudaGetSymbolAddress((void**)&xlo, g_xlo);
    cudaGetSymbolAddress((void**)&w0hi, g_w0hi); cudaGetSymbolAddress((void**)&w0lo, g_w0lo);
    cudaGetSymbolAddress((void**)&w1hi, g_w1hi); cudaGetSymbolAddress((void**)&w1lo, g_w1lo);
    cudaGetSymbolAddress((void**)&w2hi, g_w2hi); cudaGetSymbolAddress((void**)&w2lo, g_w2lo);
    cudaGetSymbolAddress((void**)&h0hi, g_h0hi); cudaGetSymbolAddress((void**)&h0lo, g_h0lo);
    cudaGetSymbolAddress((void**)&h1hi, g_h1hi); cudaGetSymbolAddress((void**)&h1lo, g_h1lo);
    cudaGetSymbolAddress((void**)&h2hi, g_h2hi); cudaGetSymbolAddress((void**)&h2lo, g_h2lo);
    cudaGetSymbolAddress((void**)&whi, g_whi);   cudaGetSymbolAddress((void**)&wlo, g_wlo);

    static cudaStream_t sB = nullptr;
    static cudaEvent_t evFork = nullptr, evJoin = nullptr;
    if (sB == nullptr) {
        cudaStreamCreateWithFlags(&sB, cudaStreamNonBlocking);
        cudaEventCreateWithFlags(&evFork, cudaEventDisableTiming);
        cudaEventCreateWithFlags(&evJoin, cudaEventDisableTiming);
        cudaFuncSetAttribute(gemm_mma_kernel,
                             cudaFuncAttributeMaxDynamicSharedMemorySize, 98304);
        cudaFuncSetAttribute(layer_kernel<DIN, 0>,
                             cudaFuncAttributeMaxDynamicSharedMemorySize, 36864);
        cudaFuncSetAttribute(layer_kernel<HID, 1>,
                             cudaFuncAttributeMaxDynamicSharedMemorySize, 36864);
    }

    // Fork: split_wout on secondary stream, overlapping prep + layers.
    cudaEventRecord(evFork, 0);
    cudaStreamWaitEvent(sB, evFork, 0);
    split_wout_kernel<<<NOUT * HID / 4 / 256, 256, 0, sB>>>(Wout);
    cudaEventRecord(evJoin, sB);

    // Main chain on default stream.
    prep_kernel<<<896, 256>>>(x, W0, W1, W2);

    layer_kernel<DIN, 0><<<dim3(HID / 64, BATCH / 32), 128, 36864>>>(
        xhi, xlo, w0hi, w0lo, b0, h0hi, h0lo);
    layer_kernel<HID, 1><<<dim3(HID / 64, BATCH / 32), 128, 36864>>>(
        h0hi, h0lo, w1hi, w1lo, b1, h1hi, h1lo);
    layer_kernel<HID, 1><<<dim3(HID / 64, BATCH / 32), 128, 36864>>>(
        h1hi, h1lo, w2hi, w2lo, b2, h2hi, h2lo);

    // Join: gemm needs whi/wlo from split_wout.
    cudaStreamWaitEvent(0, evJoin, 0);
    gemm_mma_kernel<<<dim3(NOUT / 128, BATCH / 128), 256, 98304>>>(
        h2hi, h2lo, whi, wlo, bout, theta);

    chain_kernel<<<BATCH / 8, 128>>>(x, theta, ulpa, out);
}

// round 13
// speedup vs baseline: 1.6652x; 1.0486x over previous
#include <cuda_runtime.h>
#include <cuda_bf16.h>
#include <cuda_fp16.h>
#include <math.h>
#include <stdint.h>

#define BATCH 1024
#define DIN   256
#define HID   512
#define KOUT  32
#define NOUT  (DIN * KOUT)  // 8192

typedef __nv_bfloat16 bf16;

// Scratch (allocation-free rule -> __device__ globals)
__device__ bf16 g_xhi[BATCH * DIN],  g_xlo[BATCH * DIN];
__device__ bf16 g_w0hi[HID * DIN],   g_w0lo[HID * DIN];
__device__ bf16 g_w1hi[HID * HID],   g_w1lo[HID * HID];
__device__ bf16 g_w2hi[HID * HID],   g_w2lo[HID * HID];
__device__ bf16 g_h0hi[BATCH * HID], g_h0lo[BATCH * HID];
__device__ bf16 g_h1hi[BATCH * HID], g_h1lo[BATCH * HID];
__device__ half g_h2f16[BATCH * HID];
__device__ half g_wh16[NOUT * HID], g_wl16[NOUT * HID];

// ---------------------------------------------------------------------------
// PTX helpers (sm_80-baseline: ldmatrix / mma.sync / cp.async — tcgen05 is
// rejected by this toolchain's compute_103 stage; IMMA k32 measured 2x cost)
// ---------------------------------------------------------------------------
__device__ __forceinline__ uint32_t smem_u32(const void* p) {
    uint32_t a;
    asm("{ .reg .u64 t; cvta.to.shared.u64 t, %1; cvt.u32.u64 %0, t; }" : "=r"(a) : "l"(p));
    return a;
}
__device__ __forceinline__ void ldm_x4(uint32_t* r, uint32_t addr) {
    asm volatile("ldmatrix.sync.aligned.m8n8.x4.shared.b16 {%0,%1,%2,%3}, [%4];"
                 : "=r"(r[0]), "=r"(r[1]), "=r"(r[2]), "=r"(r[3]) : "r"(addr));
}
__device__ __forceinline__ void mma_bf16(float* d, const uint32_t* a, const uint32_t* b) {
    asm volatile("mma.sync.aligned.m16n8k16.row.col.f32.bf16.bf16.f32 "
                 "{%0,%1,%2,%3}, {%4,%5,%6,%7}, {%8,%9}, {%0,%1,%2,%3};"
                 : "+f"(d[0]), "+f"(d[1]), "+f"(d[2]), "+f"(d[3])
                 : "r"(a[0]), "r"(a[1]), "r"(a[2]), "r"(a[3]), "r"(b[0]), "r"(b[1]));
}
__device__ __forceinline__ void mma_f16(float* d, const uint32_t* a, const uint32_t* b) {
    asm volatile("mma.sync.aligned.m16n8k16.row.col.f32.f16.f16.f32 "
                 "{%0,%1,%2,%3}, {%4,%5,%6,%7}, {%8,%9}, {%0,%1,%2,%3};"
                 : "+f"(d[0]), "+f"(d[1]), "+f"(d[2]), "+f"(d[3])
                 : "r"(a[0]), "r"(a[1]), "r"(a[2]), "r"(a[3]), "r"(b[0]), "r"(b[1]));
}
__device__ __forceinline__ void cp16(uint32_t dst, const void* src) {
    asm volatile("cp.async.cg.shared.global [%0], [%1], 16;" :: "r"(dst), "l"(src) : "memory");
}
__device__ __forceinline__ void cp_commit() {
    asm volatile("cp.async.commit_group;" ::: "memory");
}
template<int N> __device__ __forceinline__ void cp_wait() {
    asm volatile("cp.async.wait_group %0;" :: "n"(N) : "memory");
}
__device__ __forceinline__ void split2(float v, bf16& h, bf16& l) {
    h = __float2bfloat16(v);
    l = __float2bfloat16(v - __bfloat162float(h));
}
// min of (k % 255) over k in [a, a+32)
__device__ __forceinline__ int minmod255(int a) {
    return ((a + 31) / 255 > a / 255) ? 0 : (a % 255);
}

// ---------------------------------------------------------------------------
// Prep: split x, W0, W1, W2 into bf16 hi/lo with masks folded in.
// ---------------------------------------------------------------------------
__global__ void __launch_bounds__(256) prep_kernel(
    const float* __restrict__ x,  const float* __restrict__ W0,
    const float* __restrict__ W1, const float* __restrict__ W2)
{
    int t = blockIdx.x * 256 + threadIdx.x;
    const float* src; bf16 *hi, *lo;
    int mode, ksh, base;
    if (t < 65536)       { src = x;  hi = g_xhi;  lo = g_xlo;  mode = -1; ksh = 8; base = t * 4; }
    else if (t < 98304)  { src = W0; hi = g_w0hi; lo = g_w0lo; mode = 0;  ksh = 8; base = (t - 65536) * 4; }
    else if (t < 163840) { src = W1; hi = g_w1hi; lo = g_w1lo; mode = 1;  ksh = 9; base = (t - 98304) * 4; }
    else                 { src = W2; hi = g_w2hi; lo = g_w2lo; mode = 1;  ksh = 9; base = (t - 163840) * 4; }

    float4 v4 = *(const float4*)(src + base);
    float vv[4] = {v4.x, v4.y, v4.z, v4.w};
    int n = base >> ksh;
    int k0 = base & ((1 << ksh) - 1);
    int nd = n % 255;
    bf16 h[4], l[4];
    #pragma unroll
    for (int q = 0; q < 4; q++) {
        float v = vv[q];
        int k = k0 + q;
        if (mode == 0 && !(nd >= k)) v = 0.0f;
        if (mode == 1 && !(nd >= (k % 255))) v = 0.0f;
        split2(v, h[q], l[q]);
    }
    *(uint2*)(hi + base) = *(uint2*)h;
    *(uint2*)(lo + base) = *(uint2*)l;
}

// Wout split with output mask (MODE 2) -> fp16 hi/lo
__global__ void __launch_bounds__(256) split_wout_kernel(const float* __restrict__ W)
{
    int idx = blockIdx.x * 256 + threadIdx.x;
    int base = idx * 4;
    int n = base >> 9, k0 = base & 511;
    int od = (n >> 5) - 1;
    float4 w4 = *(const float4*)(W + base);
    float wv[4] = {w4.x, w4.y, w4.z, w4.w};
    half h[4], l[4];
    #pragma unroll
    for (int q = 0; q < 4; q++) {
        float v = (od >= ((k0 + q) % 255)) ? wv[q] : 0.0f;
        h[q] = __float2half(v);
        l[q] = __float2half(v - __half2float(h[q]));
    }
    *(uint2*)(g_wh16 + base) = *(uint2*)h;
    *(uint2*)(g_wl16 + base) = *(uint2*)l;
}

// ---------------------------------------------------------------------------
// Small-layer HMMA kernel: C = relu(A @ W^T + b).
// EMITF16=false: split epilogue -> Chi/Clo (bf16 hi/lo, feeds next bf16 layer)
// EMITF16=true : epilogue -> Cf16 (fp16, feeds the fp16 gemm)
// Tile 32m x 64n, BK=32, 128 threads, 3-stage cp.async, chunk-skip.
// (R7 champion compute config.)
// ---------------------------------------------------------------------------
template<int K, int MODE, bool EMITF16>
__global__ void __launch_bounds__(128) layer_kernel(
    const bf16* __restrict__ Ahi, const bf16* __restrict__ Alo,
    const bf16* __restrict__ Whi, const bf16* __restrict__ Wlo,
    const float* __restrict__ bias,
    bf16* __restrict__ Chi, bf16* __restrict__ Clo, half* __restrict__ Cf16)
{
    constexpr int NC = K / 32;
    constexpr int S = 3;
    constexpr uint32_t STG = 12288;
    extern __shared__ bf16 smL[];
    const int tid = threadIdx.x, lane = tid & 31, wn = tid >> 5;
    const int bm = blockIdx.y * 32;
    const int bn = ((int)gridDim.x - 1 - (int)blockIdx.x) * 64;
    const uint32_t sb = smem_u32(smL);

    const int md = (bn / 255 == (bn + 63) / 255) ? ((bn + 63) % 255) : 254;

    int act[NC]; int na = 0;
    #pragma unroll
    for (int kc = 0; kc < NC; kc++) {
        int mm = (MODE == 0) ? (32 * kc) : minmod255(32 * kc);
        if (md >= mm) act[na++] = kc;
    }

    auto load_stage = [&](int s, int kc) {
        uint32_t stg = sb + (uint32_t)s * STG;
        {
            int r = tid >> 2, c = tid & 3;
            uint32_t dsw = (uint32_t)(r * 64 + ((c ^ ((r >> 1) & 3)) << 4));
            size_t asrc = (size_t)(bm + r) * K + kc * 32 + c * 8;
            cp16(stg + dsw,         Ahi + asrc);
            cp16(stg + 2048u + dsw, Alo + asrc);
        }
        #pragma unroll
        for (int i = 0; i < 2; i++) {
            int idx = tid + i * 128;
            int r = idx >> 2, c = idx & 3;
            uint32_t dsw = (uint32_t)(r * 64 + ((c ^ ((r >> 1) & 3)) << 4));
            size_t wsrc = (size_t)(bn + r) * K + kc * 32 + c * 8;
            cp16(stg + 4096u + dsw, Whi + wsrc);
            cp16(stg + 8192u + dsw, Wlo + wsrc);
        }
    };

    int raby[2], swa[2];
    #pragma unroll
    for (int mi = 0; mi < 2; mi++) {
        int r = mi * 16 + (lane & 15);
        raby[mi] = r * 64;
        swa[mi] = (r >> 1) & 3;
    }
    const int hiA = lane >> 4;
    const int nloc = wn * 16 + (((lane >> 3) >> 1) << 3) + (lane & 7);
    const int rbby = nloc * 64, swb = (nloc >> 1) & 3, cbB = (lane >> 3) & 1;

    float acc[2][2][4];
    #pragma unroll
    for (int a = 0; a < 2; a++)
        #pragma unroll
        for (int bq = 0; bq < 2; bq++)
            #pragma unroll
            for (int q = 0; q < 4; q++) acc[a][bq][q] = 0.0f;

    #pragma unroll
    for (int s = 0; s < S - 1; s++) { if (s < na) load_stage(s, act[s]); cp_commit(); }

    #pragma unroll 1
    for (int ii = 0; ii < na; ii++) {
        cp_wait<S - 2>();
        __syncthreads();
        int ld = ii + S - 1;
        if (ld < na) load_stage(ld % S, act[ld]);
        cp_commit();

        uint32_t stg = sb + (uint32_t)(ii % S) * STG;
        #pragma unroll
        for (int k16 = 0; k16 < 2; k16++) {
            uint32_t a0[2][4], a1[2][4];
            #pragma unroll
            for (int mi = 0; mi < 2; mi++) {
                uint32_t off = (uint32_t)(raby[mi] + ((((k16 << 1) | hiA) ^ swa[mi]) << 4));
                ldm_x4(a0[mi], stg + off);
                ldm_x4(a1[mi], stg + 2048u + off);
            }
            uint32_t boff = (uint32_t)(rbby + ((((k16 << 1) | cbB) ^ swb) << 4));
            uint32_t bh[4];
            ldm_x4(bh, stg + 4096u + boff);
            #pragma unroll
            for (int mi = 0; mi < 2; mi++) {
                mma_bf16(acc[mi][0], a0[mi], &bh[0]);
                mma_bf16(acc[mi][1], a0[mi], &bh[2]);
                mma_bf16(acc[mi][0], a1[mi], &bh[0]);
                mma_bf16(acc[mi][1], a1[mi], &bh[2]);
            }
            uint32_t bl[4];
            ldm_x4(bl, stg + 8192u + boff);
            #pragma unroll
            for (int mi = 0; mi < 2; mi++) {
                mma_bf16(acc[mi][0], a0[mi], &bl[0]);
                mma_bf16(acc[mi][1], a0[mi], &bl[2]);
            }
        }
    }
    cp_wait<0>();

    const int r0 = bm + (lane >> 2);
    const int c0 = bn + wn * 16 + (lane & 3) * 2;
    #pragma unroll
    for (int mi = 0; mi < 2; mi++) {
        #pragma unroll
        for (int nj = 0; nj < 2; nj++) {
            int c = c0 + nj * 8;
            float b0 = bias[c], b1 = bias[c + 1];
            float v00 = fmaxf(acc[mi][nj][0] + b0, 0.0f);
            float v01 = fmaxf(acc[mi][nj][1] + b1, 0.0f);
            float v10 = fmaxf(acc[mi][nj][2] + b0, 0.0f);
            float v11 = fmaxf(acc[mi][nj][3] + b1, 0.0f);
            size_t o0 = (size_t)(r0 + mi * 16) * HID + c;
            size_t o1 = (size_t)(r0 + mi * 16 + 8) * HID + c;
            if (EMITF16) {
                *(half2*)(Cf16 + o0) = __floats2half2_rn(v00, v01);
                *(half2*)(Cf16 + o1) = __floats2half2_rn(v10, v11);
            } else {
                bf16 h0, l0, h1, l1;
                split2(v00, h0, l0); split2(v01, h1, l1);
                *(__nv_bfloat162*)(Chi + o0) = __halves2bfloat162(h0, h1);
                *(__nv_bfloat162*)(Clo + o0) = __halves2bfloat162(l0, l1);
                split2(v10, h0, l0); split2(v11, h1, l1);
                *(__nv_bfloat162*)(Chi + o1) = __halves2bfloat162(h0, h1);
                *(__nv_bfloat162*)(Clo + o1) = __halves2bfloat162(l0, l1);
            }
        }
    }
}

// ---------------------------------------------------------------------------
// Big fp16 HMMA GEMM: theta[1024,8192] = h2f16 @ (Wh+Wl)^T + bout (2 terms).
// Tile 128x128, BK=32, 256 threads, 3-stage pipeline (24KB/stage),
// chunk-skip by mask, heavy tiles first. 64 HMMA/warp/chunk (was 96).
// ---------------------------------------------------------------------------
__global__ void __launch_bounds__(256) gemm_f16_kernel(
    const half* __restrict__ Af, const half* __restrict__ Wh,
    const half* __restrict__ Wl,
    const float* __restrict__ bias, float* __restrict__ C)
{
    constexpr int NC = HID / 32;   // 16
    constexpr int S = 3;
    constexpr uint32_t STG = 24576;
    extern __shared__ half smd[];
    const int tid = threadIdx.x, lane = tid & 31, wrp = tid >> 5;
    const int wm = wrp >> 2, wn = wrp & 3;
    const int bm = blockIdx.y * 128;
    const int bn = ((int)gridDim.x - 1 - (int)blockIdx.x) * 128;
    const uint32_t sb = smem_u32(smd);

    const int T = (bn >> 5) + 2;
    int act[NC]; int na = 0;
    #pragma unroll
    for (int kc = 0; kc < NC; kc++)
        if (minmod255(32 * kc) <= T) act[na++] = kc;

    auto load_stage = [&](int s, int kc) {
        uint32_t stg = sb + (uint32_t)s * STG;
        #pragma unroll
        for (int i = 0; i < 2; i++) {
            int idx = tid + i * 256;
            int r = idx >> 2, c = idx & 3;
            uint32_t dsw = (uint32_t)(r * 64 + ((c ^ ((r >> 1) & 3)) << 4));
            size_t asrc = (size_t)(bm + r) * HID + kc * 32 + c * 8;
            size_t wsrc = (size_t)(bn + r) * HID + kc * 32 + c * 8;
            cp16(stg + dsw,          Af + asrc);
            cp16(stg + 8192u + dsw,  Wh + wsrc);
            cp16(stg + 16384u + dsw, Wl + wsrc);
        }
    };

    int raby[4], swa[4];
    #pragma unroll
    for (int mi = 0; mi < 4; mi++) {
        int r = wm * 64 + mi * 16 + (lane & 15);
        raby[mi] = r * 64;
        swa[mi] = (r >> 1) & 3;
    }
    const int hiA = lane >> 4;
    int rbby[2], swb[2];
    #pragma unroll
    for (int p = 0; p < 2; p++) {
        int n = wn * 32 + p * 16 + (((lane >> 3) >> 1) << 3) + (lane & 7);
        rbby[p] = n * 64;
        swb[p] = (n >> 1) & 3;
    }
    const int cbB = (lane >> 3) & 1;

    float acc[4][4][4];
    #pragma unroll
    for (int a = 0; a < 4; a++)
        #pragma unroll
        for (int bq = 0; bq < 4; bq++)
            #pragma unroll
            for (int q = 0; q < 4; q++) acc[a][bq][q] = 0.0f;

    #pragma unroll
    for (int s = 0; s < S - 1; s++) { if (s < na) load_stage(s, act[s]); cp_commit(); }

    #pragma unroll 1
    for (int ii = 0; ii < na; ii++) {
        cp_wait<S - 2>();
        __syncthreads();
        int ld = ii + S - 1;
        if (ld < na) load_stage(ld % S, act[ld]);
        cp_commit();

        uint32_t stg = sb + (uint32_t)(ii % S) * STG;
        #pragma unroll
        for (int k16 = 0; k16 < 2; k16++) {
            uint32_t a[4][4];
            #pragma unroll
            for (int mi = 0; mi < 4; mi++) {
                uint32_t off = (uint32_t)(raby[mi] + ((((k16 << 1) | hiA) ^ swa[mi]) << 4));
                ldm_x4(a[mi], stg + off);
            }
            #pragma unroll
            for (int p = 0; p < 2; p++) {
                uint32_t boff = (uint32_t)(rbby[p] + ((((k16 << 1) | cbB) ^ swb[p]) << 4));
                uint32_t wh[4];
                ldm_x4(wh, stg + 8192u + boff);
                #pragma unroll
                for (int mi = 0; mi < 4; mi++) {
                    mma_f16(acc[mi][p * 2 + 0], a[mi], &wh[0]);
                    mma_f16(acc[mi][p * 2 + 1], a[mi], &wh[2]);
                }
                uint32_t wl[4];
                ldm_x4(wl, stg + 16384u + boff);
                #pragma unroll
                for (int mi = 0; mi < 4; mi++) {
                    mma_f16(acc[mi][p * 2 + 0], a[mi], &wl[0]);
                    mma_f16(acc[mi][p * 2 + 1], a[mi], &wl[2]);
                }
            }
        }
    }
    cp_wait<0>();

    const int r0 = bm + wm * 64 + (lane >> 2);
    const int cbase = bn + wn * 32 + (lane & 3) * 2;
    #pragma unroll
    for (int mi = 0; mi < 4; mi++) {
        #pragma unroll
        for (int nj = 0; nj < 4; nj++) {
            int col = cbase + nj * 8;
            float b0 = bias[col], b1 = bias[col + 1];
            float2 v0 = {acc[mi][nj][0] + b0, acc[mi][nj][1] + b1};
            float2 v1 = {acc[mi][nj][2] + b0, acc[mi][nj][3] + b1};
            *(float2*)(C + (size_t)(r0 + mi * 16) * NOUT + col)     = v0;
            *(float2*)(C + (size_t)(r0 + mi * 16 + 8) * NOUT + col) = v1;
        }
    }
}

// ---------------------------------------------------------------------------
// Fused log_px + forward chain. 16 lanes/batch, 2 batches/warp. (Unchanged.)
// ---------------------------------------------------------------------------
__global__ void __launch_bounds__(128) chain_kernel(
    const float* __restrict__ x, const float* __restrict__ theta,
    const float* __restrict__ ulpa, float* __restrict__ out)
{
    __shared__ float s_lpa[255 * 4];
    for (int d = threadIdx.x; d < 255; d += 128) {
        float u0 = ulpa[d * 4 + 0], u1 = ulpa[d * 4 + 1];
        float u2 = ulpa[d * 4 + 2], u3 = ulpa[d * 4 + 3];
        float m = fmaxf(fmaxf(u0, u1), fmaxf(u2, u3));
        float s = expf(u0 - m) + expf(u1 - m) + expf(u2 - m) + expf(u3 - m);
        float lse = m + logf(s);
        s_lpa[d * 4 + 0] = u0 - lse;
        s_lpa[d * 4 + 1] = u1 - lse;
        s_lpa[d * 4 + 2] = u2 - lse;
        s_lpa[d * 4 + 3] = u3 - lse;
    }
    __syncthreads();

    const int lane = threadIdx.x & 31;
    const int wid  = threadIdx.x >> 5;
    const int half_ = lane >> 4;
    const int l    = lane & 15;
    const int i    = l >> 2, j = l & 3;
    const int b    = (blockIdx.x * 4 + wid) * 2 + half_;

    const unsigned FULL = 0xffffffffu;
    const float NL = -0.91893853320467274178f;

    const float* th = theta + (size_t)b * NOUT;
    const float* xb = x + (size_t)b * DIN;

    float carry;
    {
        float mu = __ldg(th + l), ls = __ldg(th + 16 + l);
        float xd = __ldg(xb);
        float sd = __expf(ls) + 0.01f;
        float z = __fdividef(xd - mu, sd);
        float lp = fmaf(-0.5f * z, z, NL) - __logf(sd);
        float v = lp + s_lpa[j];
        carry = __shfl_sync(FULL, v, half_ * 16 + j);
    }
    float mu = __ldg(th + 32 + l), ls = __ldg(th + 48 + l);
    float xd = __ldg(xb + 1);
    #pragma unroll 1
    for (int d = 1; d < 255; d++) {
        float nmu = __ldg(th + (d + 1) * 32 + l);
        float nls = __ldg(th + (d + 1) * 32 + 16 + l);
        float nxd = __ldg(xb + d + 1);
        float sd = __expf(ls) + 0.01f;
        float z = __fdividef(xd - mu, sd);
        float lp = fmaf(-0.5f * z, z, NL) - __logf(sd);
        float ci = __shfl_sync(FULL, carry, half_ * 16 + i);
        float tv = ci + lp + s_lpa[d * 4 + j];
        float m = fmaxf(tv, __shfl_xor_sync(FULL, tv, 4));
        m = fmaxf(m, __shfl_xor_sync(FULL, m, 8));
        float s = __expf(tv - m);
        s += __shfl_xor_sync(FULL, s, 4);
        s += __shfl_xor_sync(FULL, s, 8);
        carry = m + __logf(s);
        mu = nmu; ls = nls; xd = nxd;
    }
    {
        float sd = __expf(ls) + 0.01f;
        float z = __fdividef(xd - mu, sd);
        float lp = fmaf(-0.5f * z, z, NL) - __logf(sd);
        float ci = __shfl_sync(FULL, carry, half_ * 16 + i);
        float tv = (j == 0) ? (ci + lp) : -1e30f;
        float m = fmaxf(tv, __shfl_xor_sync(FULL, tv, 1));
        m = fmaxf(m, __shfl_xor_sync(FULL, m, 2));
        m = fmaxf(m, __shfl_xor_sync(FULL, m, 4));
        m = fmaxf(m, __shfl_xor_sync(FULL, m, 8));
        float s = __expf(tv - m);
        s += __shfl_xor_sync(FULL, s, 1);
        s += __shfl_xor_sync(FULL, s, 2);
        s += __shfl_xor_sync(FULL, s, 4);
        s += __shfl_xor_sync(FULL, s, 8);
        if (l == 0) out[b] = m + __logf(s);
    }
}

// ---------------------------------------------------------------------------
// kernel_launch (serial R7 schedule; only the big gemm changed to fp16 2-term)
// ---------------------------------------------------------------------------
extern "C" void kernel_launch(void* const* d_in, const int* in_sizes, int n_in,
                              void* d_out, int out_size)
{
    const float* x    = (const float*)d_in[0];
    const float* W0   = (const float*)d_in[1];
    const float* b0   = (const float*)d_in[2];
    const float* W1   = (const float*)d_in[3];
    const float* b1   = (const float*)d_in[4];
    const float* W2   = (const float*)d_in[5];
    const float* b2   = (const float*)d_in[6];
    const float* Wout = (const float*)d_in[7];
    const float* bout = (const float*)d_in[8];
    const float* ulpa = (const float*)d_in[9];

    float* out   = (float*)d_out;
    float* theta = out + BATCH;

    bf16 *xhi, *xlo, *w0hi, *w0lo, *w1hi, *w1lo, *w2hi, *w2lo;
    bf16 *h0hi, *h0lo, *h1hi, *h1lo;
    half *h2f, *wh16, *wl16;
    cudaGetSymbolAddress((void**)&xhi, g_xhi);   cudaGetSymbolAddress((void**)&xlo, g_xlo);
    cudaGetSymbolAddress((void**)&w0hi, g_w0hi); cudaGetSymbolAddress((void**)&w0lo, g_w0lo);
    cudaGetSymbolAddress((void**)&w1hi, g_w1hi); cudaGetSymbolAddress((void**)&w1lo, g_w1lo);
    cudaGetSymbolAddress((void**)&w2hi, g_w2hi); cudaGetSymbolAddress((void**)&w2lo, g_w2lo);
    cudaGetSymbolAddress((void**)&h0hi, g_h0hi); cudaGetSymbolAddress((void**)&h0lo, g_h0lo);
    cudaGetSymbolAddress((void**)&h1hi, g_h1hi); cudaGetSymbolAddress((void**)&h1lo, g_h1lo);
    cudaGetSymbolAddress((void**)&h2f, g_h2f16);
    cudaGetSymbolAddress((void**)&wh16, g_wh16); cudaGetSymbolAddress((void**)&wl16, g_wl16);

    cudaFuncSetAttribute(gemm_f16_kernel,
                         cudaFuncAttributeMaxDynamicSharedMemorySize, 73728);
    cudaFuncSetAttribute(layer_kernel<DIN, 0, false>,
                         cudaFuncAttributeMaxDynamicSharedMemorySize, 36864);
    cudaFuncSetAttribute(layer_kernel<HID, 1, false>,
                         cudaFuncAttributeMaxDynamicSharedMemorySize, 36864);
    cudaFuncSetAttribute(layer_kernel<HID, 1, true>,
                         cudaFuncAttributeMaxDynamicSharedMemorySize, 36864);

    split_wout_kernel<<<NOUT * HID / 4 / 256, 256>>>(Wout);
    prep_kernel<<<896, 256>>>(x, W0, W1, W2);

    layer_kernel<DIN, 0, false><<<dim3(HID / 64, BATCH / 32), 128, 36864>>>(
        xhi, xlo, w0hi, w0lo, b0, h0hi, h0lo, nullptr);
    layer_kernel<HID, 1, false><<<dim3(HID / 64, BATCH / 32), 128, 36864>>>(
        h0hi, h0lo, w1hi, w1lo, b1, h1hi, h1lo, nullptr);
    layer_kernel<HID, 1, true><<<dim3(HID / 64, BATCH / 32), 128, 36864>>>(
        h1hi, h1lo, w2hi, w2lo, b2, nullptr, nullptr, h2f);

    gemm_f16_kernel<<<dim3(NOUT / 128, BATCH / 128), 256, 73728>>>(
        h2f, wh16, wl16, bout, theta);

    chain_kernel<<<BATCH / 8, 128>>>(x, theta, ulpa, out);
}

// round 14
// speedup vs baseline: 1.9885x; 1.1942x over previous
#include <cuda_runtime.h>
#include <cuda_bf16.h>
#include <cuda_fp16.h>
#include <math.h>
#include <stdint.h>

#define BATCH 1024
#define DIN   256
#define HID   512
#define KOUT  32
#define NOUT  (DIN * KOUT)  // 8192

// Scratch (allocation-free rule -> __device__ globals), all fp16 now
__device__ half g_xq[BATCH * DIN];
__device__ half g_w0q[HID * DIN];
__device__ half g_w1q[HID * HID];
__device__ half g_w2q[HID * HID];
__device__ half g_h0q[BATCH * HID];
__device__ half g_h1q[BATCH * HID];
__device__ half g_h2q[BATCH * HID];
__device__ half g_wq[NOUT * HID];

// ---------------------------------------------------------------------------
// PTX helpers (sm_80-baseline: ldmatrix / mma.sync / cp.async — tcgen05 is
// rejected by this toolchain's compute_103 stage; IMMA k32 measured 2x cost)
// ---------------------------------------------------------------------------
__device__ __forceinline__ uint32_t smem_u32(const void* p) {
    uint32_t a;
    asm("{ .reg .u64 t; cvta.to.shared.u64 t, %1; cvt.u32.u64 %0, t; }" : "=r"(a) : "l"(p));
    return a;
}
__device__ __forceinline__ void ldm_x4(uint32_t* r, uint32_t addr) {
    asm volatile("ldmatrix.sync.aligned.m8n8.x4.shared.b16 {%0,%1,%2,%3}, [%4];"
                 : "=r"(r[0]), "=r"(r[1]), "=r"(r[2]), "=r"(r[3]) : "r"(addr));
}
__device__ __forceinline__ void mma_f16(float* d, const uint32_t* a, const uint32_t* b) {
    asm volatile("mma.sync.aligned.m16n8k16.row.col.f32.f16.f16.f32 "
                 "{%0,%1,%2,%3}, {%4,%5,%6,%7}, {%8,%9}, {%0,%1,%2,%3};"
                 : "+f"(d[0]), "+f"(d[1]), "+f"(d[2]), "+f"(d[3])
                 : "r"(a[0]), "r"(a[1]), "r"(a[2]), "r"(a[3]), "r"(b[0]), "r"(b[1]));
}
__device__ __forceinline__ void cp16(uint32_t dst, const void* src) {
    asm volatile("cp.async.cg.shared.global [%0], [%1], 16;" :: "r"(dst), "l"(src) : "memory");
}
__device__ __forceinline__ void cp_commit() {
    asm volatile("cp.async.commit_group;" ::: "memory");
}
template<int N> __device__ __forceinline__ void cp_wait() {
    asm volatile("cp.async.wait_group %0;" :: "n"(N) : "memory");
}
// min of (k % 255) over k in [a, a+32)
__device__ __forceinline__ int minmod255(int a) {
    return ((a + 31) / 255 > a / 255) ? 0 : (a % 255);
}

// ---------------------------------------------------------------------------
// Prep: quantize x, W0, W1, W2 to fp16 with masks folded in.
// ---------------------------------------------------------------------------
__global__ void __launch_bounds__(256) prep_kernel(
    const float* __restrict__ x,  const float* __restrict__ W0,
    const float* __restrict__ W1, const float* __restrict__ W2)
{
    int t = blockIdx.x * 256 + threadIdx.x;
    const float* src; half* dst;
    int mode, ksh, base;
    if (t < 65536)       { src = x;  dst = g_xq;  mode = -1; ksh = 8; base = t * 4; }
    else if (t < 98304)  { src = W0; dst = g_w0q; mode = 0;  ksh = 8; base = (t - 65536) * 4; }
    else if (t < 163840) { src = W1; dst = g_w1q; mode = 1;  ksh = 9; base = (t - 98304) * 4; }
    else                 { src = W2; dst = g_w2q; mode = 1;  ksh = 9; base = (t - 163840) * 4; }

    float4 v4 = *(const float4*)(src + base);
    float vv[4] = {v4.x, v4.y, v4.z, v4.w};
    int n = base >> ksh;
    int k0 = base & ((1 << ksh) - 1);
    int nd = n % 255;
    half h[4];
    #pragma unroll
    for (int q = 0; q < 4; q++) {
        float v = vv[q];
        int k = k0 + q;
        if (mode == 0 && !(nd >= k)) v = 0.0f;
        if (mode == 1 && !(nd >= (k % 255))) v = 0.0f;
        h[q] = __float2half(v);
    }
    *(uint2*)(dst + base) = *(uint2*)h;
}

// Wout quantize with output mask (MODE 2) -> fp16
__global__ void __launch_bounds__(256) split_wout_kernel(const float* __restrict__ W)
{
    int idx = blockIdx.x * 256 + threadIdx.x;
    int base = idx * 4;
    int n = base >> 9, k0 = base & 511;
    int od = (n >> 5) - 1;
    float4 w4 = *(const float4*)(W + base);
    float wv[4] = {w4.x, w4.y, w4.z, w4.w};
    half h[4];
    #pragma unroll
    for (int q = 0; q < 4; q++) {
        float v = (od >= ((k0 + q) % 255)) ? wv[q] : 0.0f;
        h[q] = __float2half(v);
    }
    *(uint2*)(g_wq + base) = *(uint2*)h;
}

// ---------------------------------------------------------------------------
// Small-layer fp16 HMMA kernel: C = relu(A @ W^T + b) -> fp16.
// Tile 32m x 64n, BK=32, 128 threads (4 warps all in n; warp = 32m x 16n).
// 1-term fp16: 4 MMA per k16. 3-stage cp.async (6KB/stage); chunk-skip.
// ---------------------------------------------------------------------------
template<int K, int MODE>
__global__ void __launch_bounds__(128) layer_kernel(
    const half* __restrict__ Aq, const half* __restrict__ Wq,
    const float* __restrict__ bias, half* __restrict__ Cq)
{
    constexpr int NC = K / 32;
    constexpr int S = 3;
    constexpr uint32_t STG = 6144;  // A 2KB + W 4KB
    extern __shared__ half smL[];
    const int tid = threadIdx.x, lane = tid & 31, wn = tid >> 5;
    const int bm = blockIdx.y * 32;
    const int bn = ((int)gridDim.x - 1 - (int)blockIdx.x) * 64;
    const uint32_t sb = smem_u32(smL);

    const int md = (bn / 255 == (bn + 63) / 255) ? ((bn + 63) % 255) : 254;

    int act[NC]; int na = 0;
    #pragma unroll
    for (int kc = 0; kc < NC; kc++) {
        int mm = (MODE == 0) ? (32 * kc) : minmod255(32 * kc);
        if (md >= mm) act[na++] = kc;
    }

    auto load_stage = [&](int s, int kc) {
        uint32_t stg = sb + (uint32_t)s * STG;
        {   // A: 32 rows x 64B
            int r = tid >> 2, c = tid & 3;
            uint32_t dsw = (uint32_t)(r * 64 + ((c ^ ((r >> 1) & 3)) << 4));
            cp16(stg + dsw, Aq + (size_t)(bm + r) * K + kc * 32 + c * 8);
        }
        #pragma unroll
        for (int i = 0; i < 2; i++) {  // W: 64 rows x 64B
            int idx = tid + i * 128;
            int r = idx >> 2, c = idx & 3;
            uint32_t dsw = (uint32_t)(r * 64 + ((c ^ ((r >> 1) & 3)) << 4));
            cp16(stg + 2048u + dsw, Wq + (size_t)(bn + r) * K + kc * 32 + c * 8);
        }
    };

    int raby[2], swa[2];
    #pragma unroll
    for (int mi = 0; mi < 2; mi++) {
        int r = mi * 16 + (lane & 15);
        raby[mi] = r * 64;
        swa[mi] = (r >> 1) & 3;
    }
    const int hiA = lane >> 4;
    const int nloc = wn * 16 + (((lane >> 3) >> 1) << 3) + (lane & 7);
    const int rbby = nloc * 64, swb = (nloc >> 1) & 3, cbB = (lane >> 3) & 1;

    float acc[2][2][4];
    #pragma unroll
    for (int a = 0; a < 2; a++)
        #pragma unroll
        for (int bq = 0; bq < 2; bq++)
            #pragma unroll
            for (int q = 0; q < 4; q++) acc[a][bq][q] = 0.0f;

    #pragma unroll
    for (int s = 0; s < S - 1; s++) { if (s < na) load_stage(s, act[s]); cp_commit(); }

    #pragma unroll 1
    for (int ii = 0; ii < na; ii++) {
        cp_wait<S - 2>();
        __syncthreads();
        int ld = ii + S - 1;
        if (ld < na) load_stage(ld % S, act[ld]);
        cp_commit();

        uint32_t stg = sb + (uint32_t)(ii % S) * STG;
        #pragma unroll
        for (int k16 = 0; k16 < 2; k16++) {
            uint32_t a0[2][4];
            #pragma unroll
            for (int mi = 0; mi < 2; mi++) {
                uint32_t off = (uint32_t)(raby[mi] + ((((k16 << 1) | hiA) ^ swa[mi]) << 4));
                ldm_x4(a0[mi], stg + off);
            }
            uint32_t boff = (uint32_t)(rbby + ((((k16 << 1) | cbB) ^ swb) << 4));
            uint32_t bh[4];
            ldm_x4(bh, stg + 2048u + boff);
            #pragma unroll
            for (int mi = 0; mi < 2; mi++) {
                mma_f16(acc[mi][0], a0[mi], &bh[0]);
                mma_f16(acc[mi][1], a0[mi], &bh[2]);
            }
        }
    }
    cp_wait<0>();

    const int r0 = bm + (lane >> 2);
    const int c0 = bn + wn * 16 + (lane & 3) * 2;
    #pragma unroll
    for (int mi = 0; mi < 2; mi++) {
        #pragma unroll
        for (int nj = 0; nj < 2; nj++) {
            int c = c0 + nj * 8;
            float b0 = bias[c], b1 = bias[c + 1];
            float v00 = fmaxf(acc[mi][nj][0] + b0, 0.0f);
            float v01 = fmaxf(acc[mi][nj][1] + b1, 0.0f);
            float v10 = fmaxf(acc[mi][nj][2] + b0, 0.0f);
            float v11 = fmaxf(acc[mi][nj][3] + b1, 0.0f);
            *(half2*)(Cq + (size_t)(r0 + mi * 16) * HID + c)     = __floats2half2_rn(v00, v01);
            *(half2*)(Cq + (size_t)(r0 + mi * 16 + 8) * HID + c) = __floats2half2_rn(v10, v11);
        }
    }
}

// ---------------------------------------------------------------------------
// Big fp16 HMMA GEMM (1-term): theta[1024,8192] = h2q @ wq^T + bout.
// Tile 128x128, BK=32, 256 threads, 3-stage pipeline (16KB/stage),
// chunk-skip by mask, heavy tiles first. 32 HMMA/warp/chunk.
// ---------------------------------------------------------------------------
__global__ void __launch_bounds__(256) gemm_f16_kernel(
    const half* __restrict__ Af, const half* __restrict__ Wf,
    const float* __restrict__ bias, float* __restrict__ C)
{
    constexpr int NC = HID / 32;   // 16
    constexpr int S = 3;
    constexpr uint32_t STG = 16384;
    extern __shared__ half smd[];
    const int tid = threadIdx.x, lane = tid & 31, wrp = tid >> 5;
    const int wm = wrp >> 2, wn = wrp & 3;
    const int bm = blockIdx.y * 128;
    const int bn = ((int)gridDim.x - 1 - (int)blockIdx.x) * 128;
    const uint32_t sb = smem_u32(smd);

    const int T = (bn >> 5) + 2;
    int act[NC]; int na = 0;
    #pragma unroll
    for (int kc = 0; kc < NC; kc++)
        if (minmod255(32 * kc) <= T) act[na++] = kc;

    auto load_stage = [&](int s, int kc) {
        uint32_t stg = sb + (uint32_t)s * STG;
        #pragma unroll
        for (int i = 0; i < 2; i++) {
            int idx = tid + i * 256;
            int r = idx >> 2, c = idx & 3;
            uint32_t dsw = (uint32_t)(r * 64 + ((c ^ ((r >> 1) & 3)) << 4));
            cp16(stg + dsw,         Af + (size_t)(bm + r) * HID + kc * 32 + c * 8);
            cp16(stg + 8192u + dsw, Wf + (size_t)(bn + r) * HID + kc * 32 + c * 8);
        }
    };

    int raby[4], swa[4];
    #pragma unroll
    for (int mi = 0; mi < 4; mi++) {
        int r = wm * 64 + mi * 16 + (lane & 15);
        raby[mi] = r * 64;
        swa[mi] = (r >> 1) & 3;
    }
    const int hiA = lane >> 4;
    int rbby[2], swb[2];
    #pragma unroll
    for (int p = 0; p < 2; p++) {
        int n = wn * 32 + p * 16 + (((lane >> 3) >> 1) << 3) + (lane & 7);
        rbby[p] = n * 64;
        swb[p] = (n >> 1) & 3;
    }
    const int cbB = (lane >> 3) & 1;

    float acc[4][4][4];
    #pragma unroll
    for (int a = 0; a < 4; a++)
        #pragma unroll
        for (int bq = 0; bq < 4; bq++)
            #pragma unroll
            for (int q = 0; q < 4; q++) acc[a][bq][q] = 0.0f;

    #pragma unroll
    for (int s = 0; s < S - 1; s++) { if (s < na) load_stage(s, act[s]); cp_commit(); }

    #pragma unroll 1
    for (int ii = 0; ii < na; ii++) {
        cp_wait<S - 2>();
        __syncthreads();
        int ld = ii + S - 1;
        if (ld < na) load_stage(ld % S, act[ld]);
        cp_commit();

        uint32_t stg = sb + (uint32_t)(ii % S) * STG;
        #pragma unroll
        for (int k16 = 0; k16 < 2; k16++) {
            uint32_t a[4][4];
            #pragma unroll
            for (int mi = 0; mi < 4; mi++) {
                uint32_t off = (uint32_t)(raby[mi] + ((((k16 << 1) | hiA) ^ swa[mi]) << 4));
                ldm_x4(a[mi], stg + off);
            }
            #pragma unroll
            for (int p = 0; p < 2; p++) {
                uint32_t boff = (uint32_t)(rbby[p] + ((((k16 << 1) | cbB) ^ swb[p]) << 4));
                uint32_t wh[4];
                ldm_x4(wh, stg + 8192u + boff);
                #pragma unroll
                for (int mi = 0; mi < 4; mi++) {
                    mma_f16(acc[mi][p * 2 + 0], a[mi], &wh[0]);
                    mma_f16(acc[mi][p * 2 + 1], a[mi], &wh[2]);
                }
            }
        }
    }
    cp_wait<0>();

    const int r0 = bm + wm * 64 + (lane >> 2);
    const int cbase = bn + wn * 32 + (lane & 3) * 2;
    #pragma unroll
    for (int mi = 0; mi < 4; mi++) {
        #pragma unroll
        for (int nj = 0; nj < 4; nj++) {
            int col = cbase + nj * 8;
            float b0 = bias[col], b1 = bias[col + 1];
            float2 v0 = {acc[mi][nj][0] + b0, acc[mi][nj][1] + b1};
            float2 v1 = {acc[mi][nj][2] + b0, acc[mi][nj][3] + b1};
            *(float2*)(C + (size_t)(r0 + mi * 16) * NOUT + col)     = v0;
            *(float2*)(C + (size_t)(r0 + mi * 16 + 8) * NOUT + col) = v1;
        }
    }
}

// ---------------------------------------------------------------------------
// Fused log_px + forward chain. 16 lanes/batch, 2 batches/warp. (Unchanged.)
// ---------------------------------------------------------------------------
__global__ void __launch_bounds__(128) chain_kernel(
    const float* __restrict__ x, const float* __restrict__ theta,
    const float* __restrict__ ulpa, float* __restrict__ out)
{
    __shared__ float s_lpa[255 * 4];
    for (int d = threadIdx.x; d < 255; d += 128) {
        float u0 = ulpa[d * 4 + 0], u1 = ulpa[d * 4 + 1];
        float u2 = ulpa[d * 4 + 2], u3 = ulpa[d * 4 + 3];
        float m = fmaxf(fmaxf(u0, u1), fmaxf(u2, u3));
        float s = expf(u0 - m) + expf(u1 - m) + expf(u2 - m) + expf(u3 - m);
        float lse = m + logf(s);
        s_lpa[d * 4 + 0] = u0 - lse;
        s_lpa[d * 4 + 1] = u1 - lse;
        s_lpa[d * 4 + 2] = u2 - lse;
        s_lpa[d * 4 + 3] = u3 - lse;
    }
    __syncthreads();

    const int lane = threadIdx.x & 31;
    const int wid  = threadIdx.x >> 5;
    const int half_ = lane >> 4;
    const int l    = lane & 15;
    const int i    = l >> 2, j = l & 3;
    const int b    = (blockIdx.x * 4 + wid) * 2 + half_;

    const unsigned FULL = 0xffffffffu;
    const float NL = -0.91893853320467274178f;

    const float* th = theta + (size_t)b * NOUT;
    const float* xb = x + (size_t)b * DIN;

    float carry;
    {
        float mu = __ldg(th + l), ls = __ldg(th + 16 + l);
        float xd = __ldg(xb);
        float sd = __expf(ls) + 0.01f;
        float z = __fdividef(xd - mu, sd);
        float lp = fmaf(-0.5f * z, z, NL) - __logf(sd);
        float v = lp + s_lpa[j];
        carry = __shfl_sync(FULL, v, half_ * 16 + j);
    }
    float mu = __ldg(th + 32 + l), ls = __ldg(th + 48 + l);
    float xd = __ldg(xb + 1);
    #pragma unroll 1
    for (int d = 1; d < 255; d++) {
        float nmu = __ldg(th + (d + 1) * 32 + l);
        float nls = __ldg(th + (d + 1) * 32 + 16 + l);
        float nxd = __ldg(xb + d + 1);
        float sd = __expf(ls) + 0.01f;
        float z = __fdividef(xd - mu, sd);
        float lp = fmaf(-0.5f * z, z, NL) - __logf(sd);
        float ci = __shfl_sync(FULL, carry, half_ * 16 + i);
        float tv = ci + lp + s_lpa[d * 4 + j];
        float m = fmaxf(tv, __shfl_xor_sync(FULL, tv, 4));
        m = fmaxf(m, __shfl_xor_sync(FULL, m, 8));
        float s = __expf(tv - m);
        s += __shfl_xor_sync(FULL, s, 4);
        s += __shfl_xor_sync(FULL, s, 8);
        carry = m + __logf(s);
        mu = nmu; ls = nls; xd = nxd;
    }
    {
        float sd = __expf(ls) + 0.01f;
        float z = __fdividef(xd - mu, sd);
        float lp = fmaf(-0.5f * z, z, NL) - __logf(sd);
        float ci = __shfl_sync(FULL, carry, half_ * 16 + i);
        float tv = (j == 0) ? (ci + lp) : -1e30f;
        float m = fmaxf(tv, __shfl_xor_sync(FULL, tv, 1));
        m = fmaxf(m, __shfl_xor_sync(FULL, m, 2));
        m = fmaxf(m, __shfl_xor_sync(FULL, m, 4));
        m = fmaxf(m, __shfl_xor_sync(FULL, m, 8));
        float s = __expf(tv - m);
        s += __shfl_xor_sync(FULL, s, 1);
        s += __shfl_xor_sync(FULL, s, 2);
        s += __shfl_xor_sync(FULL, s, 4);
        s += __shfl_xor_sync(FULL, s, 8);
        if (l == 0) out[b] = m + __logf(s);
    }
}

// ---------------------------------------------------------------------------
// kernel_launch (serial champion schedule; all GEMMs 1-term fp16)
// ---------------------------------------------------------------------------
extern "C" void kernel_launch(void* const* d_in, const int* in_sizes, int n_in,
                              void* d_out, int out_size)
{
    const float* x    = (const float*)d_in[0];
    const float* W0   = (const float*)d_in[1];
    const float* b0   = (const float*)d_in[2];
    const float* W1   = (const float*)d_in[3];
    const float* b1   = (const float*)d_in[4];
    const float* W2   = (const float*)d_in[5];
    const float* b2   = (const float*)d_in[6];
    const float* Wout = (const float*)d_in[7];
    const float* bout = (const float*)d_in[8];
    const float* ulpa = (const float*)d_in[9];

    float* out   = (float*)d_out;
    float* theta = out + BATCH;

    half *xq, *w0q, *w1q, *w2q, *h0q, *h1q, *h2q, *wq;
    cudaGetSymbolAddress((void**)&xq, g_xq);
    cudaGetSymbolAddress((void**)&w0q, g_w0q);
    cudaGetSymbolAddress((void**)&w1q, g_w1q);
    cudaGetSymbolAddress((void**)&w2q, g_w2q);
    cudaGetSymbolAddress((void**)&h0q, g_h0q);
    cudaGetSymbolAddress((void**)&h1q, g_h1q);
    cudaGetSymbolAddress((void**)&h2q, g_h2q);
    cudaGetSymbolAddress((void**)&wq, g_wq);

    cudaFuncSetAttribute(gemm_f16_kernel,
                         cudaFuncAttributeMaxDynamicSharedMemorySize, 49152);
    cudaFuncSetAttribute(layer_kernel<DIN, 0>,
                         cudaFuncAttributeMaxDynamicSharedMemorySize, 18432);
    cudaFuncSetAttribute(layer_kernel<HID, 1>,
                         cudaFuncAttributeMaxDynamicSharedMemorySize, 18432);

    split_wout_kernel<<<NOUT * HID / 4 / 256, 256>>>(Wout);
    prep_kernel<<<896, 256>>>(x, W0, W1, W2);

    layer_kernel<DIN, 0><<<dim3(HID / 64, BATCH / 32), 128, 18432>>>(
        xq, w0q, b0, h0q);
    layer_kernel<HID, 1><<<dim3(HID / 64, BATCH / 32), 128, 18432>>>(
        h0q, w1q, b1, h1q);
    layer_kernel<HID, 1><<<dim3(HID / 64, BATCH / 32), 128, 18432>>>(
        h1q, w2q, b2, h2q);

    gemm_f16_kernel<<<dim3(NOUT / 128, BATCH / 128), 256, 49152>>>(
        h2q, wq, bout, theta);

    chain_kernel<<<BATCH / 8, 128>>>(x, theta, ulpa, out);
}